// round 8
// baseline (speedup 1.0000x reference)
#include <cuda_runtime.h>
#include <cuda_bf16.h>
#include <cstdint>

#define EPSF 1e-5f

// Problem dims
#define NN  64
#define CC  64
#define TD  300
#define VV  25
#define SS  3
#define ICn 16
#define OCn 64
#define NCOL (TD*VV)          // 7500

// kConv tiling
#define TCB   20
#define NTCB  (TD/TCB)        // 15
#define COLSB (TCB*VV)        // 500

// kM tiling
#define NCH  5
#define KTOT (ICn*TD)         // 4800
#define KCH  (KTOT/NCH)       // 960
#define KST  64
#define NSTG (KCH/KST)        // 15

// kB tiling
#define CT    64                      // cols per block
#define NTBL  ((NCOL + CT - 1)/CT)    // 118
#define XMS   68                      // xm row stride  (banks 4*col+k)
#define WST   72                      // W row stride   (banks 8*k+o)
#define XTS   68                      // xT row stride
#define XCOLS 100                     // x cols staged (4 t's)

typedef unsigned long long u64;

__device__ __nv_bfloat162 g_ab[(size_t)NN*SS*KTOT*32];
__device__ float g_Mpart[NCH*NN*SS*VV*VV];
__device__ float g_Aadp [NN*SS*VV*VV];
__device__ float g_wdT  [SS*CC*OCn];   // [s][c][o], BN-scaled, tf32-rounded
__device__ float g_off  [OCn];

__device__ __forceinline__ float tanh_fast(float x) {
    float y;
    asm("tanh.approx.f32 %0, %1;" : "=f"(y) : "f"(x));
    return y;
}
__device__ __forceinline__ u64 pack2(float lo, float hi) {
    u64 r; asm("mov.b64 %0, {%1, %2};" : "=l"(r) : "f"(lo), "f"(hi)); return r;
}
__device__ __forceinline__ float2 unpack2(u64 p) {
    float2 r; asm("mov.b64 {%0, %1}, %2;" : "=f"(r.x), "=f"(r.y) : "l"(p)); return r;
}
__device__ __forceinline__ void fma2(u64& d, u64 a, u64 b) {
    asm("fma.rn.f32x2 %0, %1, %2, %0;" : "+l"(d) : "l"(a), "l"(b));
}
__device__ __forceinline__ uint32_t f2tf32(float x) {
    uint32_t u;
    asm("cvt.rna.tf32.f32 %0, %1;" : "=r"(u) : "f"(x));
    return u;
}
__device__ __forceinline__ void mma_tf32(float d[4],
    uint32_t a0, uint32_t a1, uint32_t a2, uint32_t a3,
    uint32_t b0, uint32_t b1)
{
    asm volatile(
        "mma.sync.aligned.m16n8k8.row.col.f32.tf32.tf32.f32 "
        "{%0,%1,%2,%3}, {%4,%5,%6,%7}, {%8,%9}, {%0,%1,%2,%3};\n"
        : "+f"(d[0]), "+f"(d[1]), "+f"(d[2]), "+f"(d[3])
        : "r"(a0), "r"(a1), "r"(a2), "r"(a3), "r"(b0), "r"(b1));
}

// ---------------------------------------------------------------------------
// kConv: a = tanh(bn(Wa x)), b = tanh(bn(Wb x)) -> g_ab (bf16 pairs).
// ---------------------------------------------------------------------------
__global__ __launch_bounds__(256) void kConv(
    const float* __restrict__ x,
    const float* __restrict__ wa, const float* __restrict__ ba,
    const float* __restrict__ wb, const float* __restrict__ bb,
    const float* __restrict__ gag, const float* __restrict__ gab,
    const float* __restrict__ gam, const float* __restrict__ gav,
    const float* __restrict__ gbg, const float* __restrict__ gbb,
    const float* __restrict__ gbm, const float* __restrict__ gbv)
{
    __shared__ __align__(16) float s_w[CC*32];
    __shared__ float s_sha[ICn], s_shb[ICn];

    const int tid = threadIdx.x;
    const int tc  = blockIdx.x;
    const int s   = blockIdx.y;
    const int n   = blockIdx.z;

    for (int idx = tid; idx < ICn*CC; idx += 256) {
        int i = idx / CC, c = idx % CC;
        float sca = gag[s*ICn+i] * rsqrtf(gav[s*ICn+i] + EPSF);
        float scb = gbg[s*ICn+i] * rsqrtf(gbv[s*ICn+i] + EPSF);
        s_w[c*32 + i]      = wa[s*ICn*CC + idx] * sca;
        s_w[c*32 + 16 + i] = wb[s*ICn*CC + idx] * scb;
    }
    if (tid < ICn) {
        float sca = gag[s*ICn+tid] * rsqrtf(gav[s*ICn+tid] + EPSF);
        float scb = gbg[s*ICn+tid] * rsqrtf(gbv[s*ICn+tid] + EPSF);
        s_sha[tid] = (ba[s*ICn+tid] - gam[s*ICn+tid]) * sca + gab[s*ICn+tid];
        s_shb[tid] = (bb[s*ICn+tid] - gbm[s*ICn+tid]) * scb + gbb[s*ICn+tid];
    }
    __syncthreads();
    if (tid >= COLSB/2) return;

    const int col0 = tc*COLSB + 2*tid;
    const int col1 = col0 + 1;
    const int t0 = col0 / 25, v0 = col0 - 25*t0;
    const int t1 = col1 / 25, v1 = col1 - 25*t1;

    u64 accA0[8], accA1[8], accB0[8], accB1[8];
    #pragma unroll
    for (int p = 0; p < 8; p++) {
        u64 ia = pack2(s_sha[2*p], s_sha[2*p+1]);
        u64 ib = pack2(s_shb[2*p], s_shb[2*p+1]);
        accA0[p] = ia; accA1[p] = ia;
        accB0[p] = ib; accB1[p] = ib;
    }

    const float* xp = x + (size_t)n*(CC*NCOL) + col0;
    #pragma unroll 4
    for (int c = 0; c < CC; c++) {
        float2 xv = *reinterpret_cast<const float2*>(xp + (size_t)c*NCOL);
        u64 xd0 = pack2(xv.x, xv.x);
        u64 xd1 = pack2(xv.y, xv.y);
        const ulonglong2* wrow = reinterpret_cast<const ulonglong2*>(&s_w[c*32]);
        #pragma unroll
        for (int g = 0; g < 4; g++) {
            ulonglong2 w2 = wrow[g];
            fma2(accA0[2*g],   w2.x, xd0); fma2(accA1[2*g],   w2.x, xd1);
            fma2(accA0[2*g+1], w2.y, xd0); fma2(accA1[2*g+1], w2.y, xd1);
        }
        #pragma unroll
        for (int g = 0; g < 4; g++) {
            ulonglong2 w2 = wrow[4+g];
            fma2(accB0[2*g],   w2.x, xd0); fma2(accB1[2*g],   w2.x, xd1);
            fma2(accB0[2*g+1], w2.y, xd0); fma2(accB1[2*g+1], w2.y, xd1);
        }
    }

    __nv_bfloat162* gb = g_ab + (size_t)(n*SS + s)*KTOT*32;
    #pragma unroll
    for (int p = 0; p < 8; p++) {
        float2 a0 = unpack2(accA0[p]);
        float2 b0 = unpack2(accB0[p]);
        float2 a1 = unpack2(accA1[p]);
        float2 b1 = unpack2(accB1[p]);
        __nv_bfloat162 h;
        h.x = __float2bfloat16(tanh_fast(a0.x));
        h.y = __float2bfloat16(tanh_fast(b0.x));
        gb[(size_t)(t0*ICn + 2*p)*32 + v0] = h;
        h.x = __float2bfloat16(tanh_fast(a0.y));
        h.y = __float2bfloat16(tanh_fast(b0.y));
        gb[(size_t)(t0*ICn + 2*p+1)*32 + v0] = h;
        h.x = __float2bfloat16(tanh_fast(a1.x));
        h.y = __float2bfloat16(tanh_fast(b1.x));
        gb[(size_t)(t1*ICn + 2*p)*32 + v1] = h;
        h.x = __float2bfloat16(tanh_fast(a1.y));
        h.y = __float2bfloat16(tanh_fast(b1.y));
        gb[(size_t)(t1*ICn + 2*p+1)*32 + v1] = h;
    }
}

// ---------------------------------------------------------------------------
// kM: partial M over 960 rows.
// ---------------------------------------------------------------------------
__global__ __launch_bounds__(256) void kM()
{
    __shared__ __align__(16) float s_a32[KST*32];
    __shared__ __align__(16) float s_b32[KST*32];

    const int tid  = threadIdx.x;
    const int wid  = tid >> 5;
    const int lane = tid & 31;
    const int chunk = blockIdx.x;
    const int s     = blockIdx.y;
    const int n     = blockIdx.z;

    const uint4* gsrc = reinterpret_cast<const uint4*>(
        g_ab + ((size_t)(n*SS + s)*KTOT + (size_t)chunk*KCH)*32);

    u64 macc[2] = {0ull, 0ull};

    for (int st = 0; st < NSTG; st++) {
        __syncthreads();
        #pragma unroll
        for (int rep = 0; rep < 2; rep++) {
            int u = tid + rep*256;
            uint4 val = gsrc[st*512 + u];
            int row = u >> 3, q = u & 7;
            float* pa = &s_a32[row*32 + q*4];
            float* pb = &s_b32[row*32 + q*4];
            float2 f0 = __bfloat1622float2(*reinterpret_cast<__nv_bfloat162*>(&val.x));
            float2 f1 = __bfloat1622float2(*reinterpret_cast<__nv_bfloat162*>(&val.y));
            float2 f2 = __bfloat1622float2(*reinterpret_cast<__nv_bfloat162*>(&val.z));
            float2 f3 = __bfloat1622float2(*reinterpret_cast<__nv_bfloat162*>(&val.w));
            pa[0] = f0.x; pb[0] = f0.y;
            pa[1] = f1.x; pb[1] = f1.y;
            pa[2] = f2.x; pb[2] = f2.y;
            pa[3] = f3.x; pb[3] = f3.y;
        }
        __syncthreads();
        #pragma unroll 8
        for (int kk = 0; kk < KST; kk++) {
            float av = s_a32[kk*32 + lane];
            u64 ap = pack2(av, av);
            ulonglong2 bv = *reinterpret_cast<const ulonglong2*>(
                &s_b32[kk*32 + wid*4]);
            fma2(macc[0], ap, bv.x);
            fma2(macc[1], ap, bv.y);
        }
    }

    if (lane < VV) {
        float* mp = &g_Mpart[((size_t)chunk*NN*SS + (size_t)n*SS + s)*(VV*VV)];
        float2 m0 = unpack2(macc[0]);
        float2 m1 = unpack2(macc[1]);
        int w = wid*4;
        if (w   < VV) mp[lane*VV + w]   = m0.x;
        if (w+1 < VV) mp[lane*VV + w+1] = m0.y;
        if (w+2 < VV) mp[lane*VV + w+2] = m1.x;
        if (w+3 < VV) mp[lane*VV + w+3] = m1.y;
    }
}

// ---------------------------------------------------------------------------
// kA2: reduce partials, A_adp = A + tanh(M/(IC*T)) * alpha
// ---------------------------------------------------------------------------
__global__ void kA2(const float* __restrict__ A, const float* __restrict__ alpha)
{
    int idx = blockIdx.x * 256 + threadIdx.x;
    if (idx >= NN*SS*VV*VV) return;
    float m = 0.f;
    #pragma unroll
    for (int ch = 0; ch < NCH; ch++)
        m += g_Mpart[ch*(NN*SS*VV*VV) + idx];
    g_Aadp[idx] = A[idx % (SS*VV*VV)]
                + tanhf(m * (1.f/(float)(ICn*TD))) * alpha[0];
}

// ---------------------------------------------------------------------------
// kW: W -> [s][c][o], BN scale folded, tf32-rounded. g_off.
// ---------------------------------------------------------------------------
__global__ void kW(const float* __restrict__ wd, const float* __restrict__ db,
                   const float* __restrict__ bng, const float* __restrict__ bnb,
                   const float* __restrict__ bnm, const float* __restrict__ bnv)
{
    int idx = blockIdx.x * 256 + threadIdx.x;
    if (idx < SS*OCn*CC) {
        int c = idx & 63;
        int o = (idx >> 6) & 63;
        int s = idx >> 12;
        float sc = bng[o] * rsqrtf(bnv[o] + EPSF);
        uint32_t t = f2tf32(wd[idx] * sc);
        g_wdT[s*(CC*OCn) + c*OCn + o] = __uint_as_float(t);
    }
    if (blockIdx.x == 0 && threadIdx.x < OCn) {
        int o = threadIdx.x;
        float sc = bng[o] * rsqrtf(bnv[o] + EPSF);
        float ds = db[o] + db[OCn + o] + db[2*OCn + o];
        g_off[o] = (ds - bnm[o]) * sc + bnb[o];
    }
}

// ---------------------------------------------------------------------------
// kB: block = (64-col tile, n). For each s:
//   GEMM1 (SIMT fp32): xm_s[col][c] = sum_v x[c][t(col)*25+v] * Aad_s[v][w(col)]
//                      written as tf32 bits, stride 68
//   GEMM2 (mma tf32):  D[col][o] += xm_s[col][c] * W_s[c][o]
// Epilogue: D + off + residual, ReLU.
// ---------------------------------------------------------------------------
__global__ __launch_bounds__(256, 2) void kB(
    const float* __restrict__ x,
    float* __restrict__ out)
{
    extern __shared__ float sm[];
    float* s_xT  = sm;                       // [100][68]  x transposed
    float* s_xm  = s_xT + XCOLS*XTS;         // [64][68]   tf32 bits
    float* s_w   = s_xm + CT*XMS;            // [192][72]  tf32 bits
    float* s_Aad = s_w  + SS*CC*WST;         // [3][25][32]
    float* s_off = s_Aad + SS*VV*32;         // [64]

    const int tid  = threadIdx.x;
    const int wid  = tid >> 5;
    const int lane = tid & 31;
    const int blk  = blockIdx.x;
    const int n    = blockIdx.y;
    const int cbase = blk * CT;
    const int t0    = cbase / VV;

    const float* xn = x + (size_t)n*(CC*NCOL);

    // ---- staging ----
    // x transposed: s_xT[xcol][c]; global xcol = t0*25 + xcol
    for (int idx = tid; idx < CC*XCOLS; idx += 256) {
        int c = idx / XCOLS, xc = idx % XCOLS;
        int gxc = t0*VV + xc;
        s_xT[xc*XTS + c] = (gxc < NCOL) ? xn[(size_t)c*NCOL + gxc] : 0.f;
    }
    // W [192][72]
    for (int idx = tid; idx < SS*CC*OCn; idx += 256) {
        int k = idx >> 6, o = idx & 63;
        s_w[k*WST + o] = g_wdT[idx];
    }
    // Aad [3][25][32]
    for (int idx = tid; idx < SS*VV*32; idx += 256) {
        int s = idx / (VV*32);
        int r = idx - s*(VV*32);
        int v = r >> 5, w = r & 31;
        s_Aad[idx] = (w < VV)
                   ? g_Aadp[((size_t)n*SS + s)*(VV*VV) + v*VV + w] : 0.f;
    }
    if (tid < OCn) s_off[tid] = g_off[tid];

    // GEMM1 mapping: p = lane (colpair), g = wid (cgroup of 8)
    const int colA = 2*(tid & 31);
    const int colB = colA + 1;
    const int c0g  = (tid >> 5) * 8;
    const int gcA  = cbase + colA;
    const int gcB  = cbase + colB;
    const int tA   = gcA / VV, wA = gcA - VV*tA;
    const int tB   = gcB / VV, wB = gcB - VV*tB;
    const int xbA  = (tA - t0) * VV;   // local xcol base for colA
    const int xbB  = (tB - t0) * VV;

    // mma mapping: warp = (ct = wid&3, oh = wid>>2)
    const int ct = wid & 3;
    const int oh = wid >> 2;
    const int gr = lane >> 2;          // 0..7
    const int tc = lane & 3;           // 0..3

    float d[4][4];
    #pragma unroll
    for (int nt = 0; nt < 4; nt++)
        #pragma unroll
        for (int j = 0; j < 4; j++) d[nt][j] = 0.f;

    const uint32_t* xmu = reinterpret_cast<const uint32_t*>(s_xm);
    const uint32_t* wu  = reinterpret_cast<const uint32_t*>(s_w);
    uint32_t* xmw = reinterpret_cast<uint32_t*>(s_xm);

    for (int s = 0; s < SS; s++) {
        __syncthreads();   // previous mma reads done
        // ---- GEMM1 ----
        {
            u64 accA[4] = {0ull,0ull,0ull,0ull};
            u64 accB[4] = {0ull,0ull,0ull,0ull};
            const float* AadS = &s_Aad[s*(VV*32)];
            #pragma unroll 5
            for (int v = 0; v < VV; v++) {
                float avA = AadS[v*32 + wA];
                float avB = AadS[v*32 + wB];
                u64 adA = pack2(avA, avA);
                u64 adB = pack2(avB, avB);
                const ulonglong2* xpA = reinterpret_cast<const ulonglong2*>(
                    &s_xT[(xbA + v)*XTS + c0g]);
                const ulonglong2* xpB = reinterpret_cast<const ulonglong2*>(
                    &s_xT[(xbB + v)*XTS + c0g]);
                ulonglong2 xa0 = xpA[0], xa1 = xpA[1];
                ulonglong2 xb0 = xpB[0], xb1 = xpB[1];
                fma2(accA[0], xa0.x, adA); fma2(accA[1], xa0.y, adA);
                fma2(accA[2], xa1.x, adA); fma2(accA[3], xa1.y, adA);
                fma2(accB[0], xb0.x, adB); fma2(accB[1], xb0.y, adB);
                fma2(accB[2], xb1.x, adB); fma2(accB[3], xb1.y, adB);
            }
            uint32_t tA8[8], tB8[8];
            #pragma unroll
            for (int k = 0; k < 4; k++) {
                float2 fa = unpack2(accA[k]);
                float2 fb = unpack2(accB[k]);
                tA8[2*k]   = f2tf32(fa.x);
                tA8[2*k+1] = f2tf32(fa.y);
                tB8[2*k]   = f2tf32(fb.x);
                tB8[2*k+1] = f2tf32(fb.y);
            }
            uint4* dstA = reinterpret_cast<uint4*>(&xmw[colA*XMS + c0g]);
            uint4* dstB = reinterpret_cast<uint4*>(&xmw[colB*XMS + c0g]);
            dstA[0] = make_uint4(tA8[0], tA8[1], tA8[2], tA8[3]);
            dstA[1] = make_uint4(tA8[4], tA8[5], tA8[6], tA8[7]);
            dstB[0] = make_uint4(tB8[0], tB8[1], tB8[2], tB8[3]);
            dstB[1] = make_uint4(tB8[4], tB8[5], tB8[6], tB8[7]);
        }
        __syncthreads();

        // ---- GEMM2 via mma: K = 64 (this s), 8 k-steps ----
        #pragma unroll 2
        for (int kq = 0; kq < 8; kq++) {
            int k = kq*8;
            uint32_t a0 = xmu[(ct*16 + gr     )*XMS + k + tc];
            uint32_t a1 = xmu[(ct*16 + gr +  8)*XMS + k + tc];
            uint32_t a2 = xmu[(ct*16 + gr     )*XMS + k + tc + 4];
            uint32_t a3 = xmu[(ct*16 + gr +  8)*XMS + k + tc + 4];
            int kgl = s*CC + k;
            #pragma unroll
            for (int nt = 0; nt < 4; nt++) {
                int o0 = oh*32 + nt*8;
                uint32_t b0 = wu[(kgl + tc    )*WST + o0 + gr];
                uint32_t b1 = wu[(kgl + tc + 4)*WST + o0 + gr];
                mma_tf32(d[nt], a0, a1, a2, a3, b0, b1);
            }
        }
    }

    // ---- epilogue ----
    {
        const int row0 = ct*16 + gr;
        const int row1 = row0 + 8;
        const int colg0 = cbase + row0;
        const int colg1 = cbase + row1;
        const bool ok0 = (colg0 < NCOL);
        const bool ok1 = (colg1 < NCOL);
        float* on = out + (size_t)n*(CC*NCOL);
        #pragma unroll
        for (int nt = 0; nt < 4; nt++) {
            int oe = oh*32 + nt*8 + 2*tc;
            int oo = oe + 1;
            float offe = s_off[oe], offo = s_off[oo];
            if (ok0) {
                float v0 = d[nt][0] + offe + xn[(size_t)oe*NCOL + colg0];
                float v1 = d[nt][1] + offo + xn[(size_t)oo*NCOL + colg0];
                on[(size_t)oe*NCOL + colg0] = fmaxf(v0, 0.f);
                on[(size_t)oo*NCOL + colg0] = fmaxf(v1, 0.f);
            }
            if (ok1) {
                float v2 = d[nt][2] + offe + xn[(size_t)oe*NCOL + colg1];
                float v3 = d[nt][3] + offo + xn[(size_t)oo*NCOL + colg1];
                on[(size_t)oe*NCOL + colg1] = fmaxf(v2, 0.f);
                on[(size_t)oo*NCOL + colg1] = fmaxf(v3, 0.f);
            }
        }
    }
}

// ---------------------------------------------------------------------------
extern "C" void kernel_launch(void* const* d_in, const int* in_sizes, int n_in,
                              void* d_out, int out_size)
{
    const float* x     = (const float*)d_in[0];
    const float* A     = (const float*)d_in[1];
    const float* alpha = (const float*)d_in[2];
    const float* caw   = (const float*)d_in[3];
    const float* cab   = (const float*)d_in[4];
    const float* cbw   = (const float*)d_in[5];
    const float* cbb   = (const float*)d_in[6];
    const float* bag   = (const float*)d_in[7];
    const float* babt  = (const float*)d_in[8];
    const float* bam   = (const float*)d_in[9];
    const float* bav   = (const float*)d_in[10];
    const float* bbg   = (const float*)d_in[11];
    const float* bbbt  = (const float*)d_in[12];
    const float* bbm   = (const float*)d_in[13];
    const float* bbv   = (const float*)d_in[14];
    const float* cdw   = (const float*)d_in[15];
    const float* cdb   = (const float*)d_in[16];
    const float* bng   = (const float*)d_in[17];
    const float* bnb   = (const float*)d_in[18];
    const float* bnm   = (const float*)d_in[19];
    const float* bnv   = (const float*)d_in[20];
    float* out = (float*)d_out;

    const int smemB = (XCOLS*XTS + CT*XMS + SS*CC*WST + SS*VV*32 + 64)
                      * sizeof(float);
    cudaFuncSetAttribute(kB, cudaFuncAttributeMaxDynamicSharedMemorySize, smemB);

    kW<<<(SS*OCn*CC + 255)/256, 256>>>(cdw, cdb, bng, bnb, bnm, bnv);
    kConv<<<dim3(NTCB, SS, NN), 256>>>(x, caw, cab, cbw, cbb,
                                       bag, babt, bam, bav,
                                       bbg, bbbt, bbm, bbv);
    kM<<<dim3(NCH, SS, NN), 256>>>();
    kA2<<<(NN*SS*VV*VV + 255)/256, 256>>>(A, alpha);
    kB<<<dim3(NTBL, NN), 256, smemB>>>(x, out);
}

// round 9
// speedup vs baseline: 1.3822x; 1.3822x over previous
#include <cuda_runtime.h>
#include <cuda_bf16.h>
#include <cstdint>

#define EPSF 1e-5f

// Problem dims
#define NN  64
#define CC  64
#define TD  300
#define VV  25
#define SS  3
#define ICn 16
#define OCn 64
#define NCOL (TD*VV)          // 7500

// kConv tiling
#define TCB   20
#define NTCB  (TD/TCB)        // 15
#define COLSB (TCB*VV)        // 500

// kM tiling
#define NCH  5
#define KTOT (ICn*TD)         // 4800
#define KCH  (KTOT/NCH)       // 960
#define KST  64
#define NSTG (KCH/KST)        // 15

// kB tiling
#define CT    64                      // cols per block
#define NTBL  ((NCOL + CT - 1)/CT)    // 118
#define XST   108                     // s_x row stride (A-frag conflict-free)
#define XMS   68                      // xm row stride
#define WST   72                      // W row stride

typedef unsigned long long u64;

__device__ __nv_bfloat162 g_ab[(size_t)NN*SS*KTOT*32];
__device__ float g_Mpart[NCH*NN*SS*VV*VV];
__device__ float g_Aadp [NN*SS*VV*VV];
__device__ float g_wdT  [SS*CC*OCn];   // [s][c][o], BN-scaled, tf32 bits
__device__ float g_off  [OCn];

__device__ __forceinline__ float tanh_fast(float x) {
    float y;
    asm("tanh.approx.f32 %0, %1;" : "=f"(y) : "f"(x));
    return y;
}
__device__ __forceinline__ u64 pack2(float lo, float hi) {
    u64 r; asm("mov.b64 %0, {%1, %2};" : "=l"(r) : "f"(lo), "f"(hi)); return r;
}
__device__ __forceinline__ float2 unpack2(u64 p) {
    float2 r; asm("mov.b64 {%0, %1}, %2;" : "=f"(r.x), "=f"(r.y) : "l"(p)); return r;
}
__device__ __forceinline__ void fma2(u64& d, u64 a, u64 b) {
    asm("fma.rn.f32x2 %0, %1, %2, %0;" : "+l"(d) : "l"(a), "l"(b));
}
__device__ __forceinline__ uint32_t f2tf32(float x) {
    uint32_t u;
    asm("cvt.rna.tf32.f32 %0, %1;" : "=r"(u) : "f"(x));
    return u;
}
__device__ __forceinline__ void mma_tf32(float d[4],
    uint32_t a0, uint32_t a1, uint32_t a2, uint32_t a3,
    uint32_t b0, uint32_t b1)
{
    asm volatile(
        "mma.sync.aligned.m16n8k8.row.col.f32.tf32.tf32.f32 "
        "{%0,%1,%2,%3}, {%4,%5,%6,%7}, {%8,%9}, {%0,%1,%2,%3};\n"
        : "+f"(d[0]), "+f"(d[1]), "+f"(d[2]), "+f"(d[3])
        : "r"(a0), "r"(a1), "r"(a2), "r"(a3), "r"(b0), "r"(b1));
}

// ---------------------------------------------------------------------------
// kConv: a = tanh(bn(Wa x)), b = tanh(bn(Wb x)) -> g_ab (bf16 pairs).
// ---------------------------------------------------------------------------
__global__ __launch_bounds__(256) void kConv(
    const float* __restrict__ x,
    const float* __restrict__ wa, const float* __restrict__ ba,
    const float* __restrict__ wb, const float* __restrict__ bb,
    const float* __restrict__ gag, const float* __restrict__ gab,
    const float* __restrict__ gam, const float* __restrict__ gav,
    const float* __restrict__ gbg, const float* __restrict__ gbb,
    const float* __restrict__ gbm, const float* __restrict__ gbv)
{
    __shared__ __align__(16) float s_w[CC*32];
    __shared__ float s_sha[ICn], s_shb[ICn];

    const int tid = threadIdx.x;
    const int tc  = blockIdx.x;
    const int s   = blockIdx.y;
    const int n   = blockIdx.z;

    for (int idx = tid; idx < ICn*CC; idx += 256) {
        int i = idx / CC, c = idx % CC;
        float sca = gag[s*ICn+i] * rsqrtf(gav[s*ICn+i] + EPSF);
        float scb = gbg[s*ICn+i] * rsqrtf(gbv[s*ICn+i] + EPSF);
        s_w[c*32 + i]      = wa[s*ICn*CC + idx] * sca;
        s_w[c*32 + 16 + i] = wb[s*ICn*CC + idx] * scb;
    }
    if (tid < ICn) {
        float sca = gag[s*ICn+tid] * rsqrtf(gav[s*ICn+tid] + EPSF);
        float scb = gbg[s*ICn+tid] * rsqrtf(gbv[s*ICn+tid] + EPSF);
        s_sha[tid] = (ba[s*ICn+tid] - gam[s*ICn+tid]) * sca + gab[s*ICn+tid];
        s_shb[tid] = (bb[s*ICn+tid] - gbm[s*ICn+tid]) * scb + gbb[s*ICn+tid];
    }
    __syncthreads();
    if (tid >= COLSB/2) return;

    const int col0 = tc*COLSB + 2*tid;
    const int col1 = col0 + 1;
    const int t0 = col0 / 25, v0 = col0 - 25*t0;
    const int t1 = col1 / 25, v1 = col1 - 25*t1;

    u64 accA0[8], accA1[8], accB0[8], accB1[8];
    #pragma unroll
    for (int p = 0; p < 8; p++) {
        u64 ia = pack2(s_sha[2*p], s_sha[2*p+1]);
        u64 ib = pack2(s_shb[2*p], s_shb[2*p+1]);
        accA0[p] = ia; accA1[p] = ia;
        accB0[p] = ib; accB1[p] = ib;
    }

    const float* xp = x + (size_t)n*(CC*NCOL) + col0;
    #pragma unroll 4
    for (int c = 0; c < CC; c++) {
        float2 xv = *reinterpret_cast<const float2*>(xp + (size_t)c*NCOL);
        u64 xd0 = pack2(xv.x, xv.x);
        u64 xd1 = pack2(xv.y, xv.y);
        const ulonglong2* wrow = reinterpret_cast<const ulonglong2*>(&s_w[c*32]);
        #pragma unroll
        for (int g = 0; g < 4; g++) {
            ulonglong2 w2 = wrow[g];
            fma2(accA0[2*g],   w2.x, xd0); fma2(accA1[2*g],   w2.x, xd1);
            fma2(accA0[2*g+1], w2.y, xd0); fma2(accA1[2*g+1], w2.y, xd1);
        }
        #pragma unroll
        for (int g = 0; g < 4; g++) {
            ulonglong2 w2 = wrow[4+g];
            fma2(accB0[2*g],   w2.x, xd0); fma2(accB1[2*g],   w2.x, xd1);
            fma2(accB0[2*g+1], w2.y, xd0); fma2(accB1[2*g+1], w2.y, xd1);
        }
    }

    __nv_bfloat162* gb = g_ab + (size_t)(n*SS + s)*KTOT*32;
    #pragma unroll
    for (int p = 0; p < 8; p++) {
        float2 a0 = unpack2(accA0[p]);
        float2 b0 = unpack2(accB0[p]);
        float2 a1 = unpack2(accA1[p]);
        float2 b1 = unpack2(accB1[p]);
        __nv_bfloat162 h;
        h.x = __float2bfloat16(tanh_fast(a0.x));
        h.y = __float2bfloat16(tanh_fast(b0.x));
        gb[(size_t)(t0*ICn + 2*p)*32 + v0] = h;
        h.x = __float2bfloat16(tanh_fast(a0.y));
        h.y = __float2bfloat16(tanh_fast(b0.y));
        gb[(size_t)(t0*ICn + 2*p+1)*32 + v0] = h;
        h.x = __float2bfloat16(tanh_fast(a1.x));
        h.y = __float2bfloat16(tanh_fast(b1.x));
        gb[(size_t)(t1*ICn + 2*p)*32 + v1] = h;
        h.x = __float2bfloat16(tanh_fast(a1.y));
        h.y = __float2bfloat16(tanh_fast(b1.y));
        gb[(size_t)(t1*ICn + 2*p+1)*32 + v1] = h;
    }
}

// ---------------------------------------------------------------------------
// kM: partial M over 960 rows.
// ---------------------------------------------------------------------------
__global__ __launch_bounds__(256) void kM()
{
    __shared__ __align__(16) float s_a32[KST*32];
    __shared__ __align__(16) float s_b32[KST*32];

    const int tid  = threadIdx.x;
    const int wid  = tid >> 5;
    const int lane = tid & 31;
    const int chunk = blockIdx.x;
    const int s     = blockIdx.y;
    const int n     = blockIdx.z;

    const uint4* gsrc = reinterpret_cast<const uint4*>(
        g_ab + ((size_t)(n*SS + s)*KTOT + (size_t)chunk*KCH)*32);

    u64 macc[2] = {0ull, 0ull};

    for (int st = 0; st < NSTG; st++) {
        __syncthreads();
        #pragma unroll
        for (int rep = 0; rep < 2; rep++) {
            int u = tid + rep*256;
            uint4 val = gsrc[st*512 + u];
            int row = u >> 3, q = u & 7;
            float* pa = &s_a32[row*32 + q*4];
            float* pb = &s_b32[row*32 + q*4];
            float2 f0 = __bfloat1622float2(*reinterpret_cast<__nv_bfloat162*>(&val.x));
            float2 f1 = __bfloat1622float2(*reinterpret_cast<__nv_bfloat162*>(&val.y));
            float2 f2 = __bfloat1622float2(*reinterpret_cast<__nv_bfloat162*>(&val.z));
            float2 f3 = __bfloat1622float2(*reinterpret_cast<__nv_bfloat162*>(&val.w));
            pa[0] = f0.x; pb[0] = f0.y;
            pa[1] = f1.x; pb[1] = f1.y;
            pa[2] = f2.x; pb[2] = f2.y;
            pa[3] = f3.x; pb[3] = f3.y;
        }
        __syncthreads();
        #pragma unroll 8
        for (int kk = 0; kk < KST; kk++) {
            float av = s_a32[kk*32 + lane];
            u64 ap = pack2(av, av);
            ulonglong2 bv = *reinterpret_cast<const ulonglong2*>(
                &s_b32[kk*32 + wid*4]);
            fma2(macc[0], ap, bv.x);
            fma2(macc[1], ap, bv.y);
        }
    }

    if (lane < VV) {
        float* mp = &g_Mpart[((size_t)chunk*NN*SS + (size_t)n*SS + s)*(VV*VV)];
        float2 m0 = unpack2(macc[0]);
        float2 m1 = unpack2(macc[1]);
        int w = wid*4;
        if (w   < VV) mp[lane*VV + w]   = m0.x;
        if (w+1 < VV) mp[lane*VV + w+1] = m0.y;
        if (w+2 < VV) mp[lane*VV + w+2] = m1.x;
        if (w+3 < VV) mp[lane*VV + w+3] = m1.y;
    }
}

// ---------------------------------------------------------------------------
// kA2: reduce partials, A_adp = A + tanh(M/(IC*T)) * alpha
// ---------------------------------------------------------------------------
__global__ void kA2(const float* __restrict__ A, const float* __restrict__ alpha)
{
    int idx = blockIdx.x * 256 + threadIdx.x;
    if (idx >= NN*SS*VV*VV) return;
    float m = 0.f;
    #pragma unroll
    for (int ch = 0; ch < NCH; ch++)
        m += g_Mpart[ch*(NN*SS*VV*VV) + idx];
    g_Aadp[idx] = A[idx % (SS*VV*VV)]
                + tanhf(m * (1.f/(float)(ICn*TD))) * alpha[0];
}

// ---------------------------------------------------------------------------
// kW: W -> [s][c][o], BN scale folded, tf32-rounded. g_off.
// ---------------------------------------------------------------------------
__global__ void kW(const float* __restrict__ wd, const float* __restrict__ db,
                   const float* __restrict__ bng, const float* __restrict__ bnb,
                   const float* __restrict__ bnm, const float* __restrict__ bnv)
{
    int idx = blockIdx.x * 256 + threadIdx.x;
    if (idx < SS*OCn*CC) {
        int c = idx & 63;
        int o = (idx >> 6) & 63;
        int s = idx >> 12;
        float sc = bng[o] * rsqrtf(bnv[o] + EPSF);
        uint32_t t = f2tf32(wd[idx] * sc);
        g_wdT[s*(CC*OCn) + c*OCn + o] = __uint_as_float(t);
    }
    if (blockIdx.x == 0 && threadIdx.x < OCn) {
        int o = threadIdx.x;
        float sc = bng[o] * rsqrtf(bnv[o] + EPSF);
        float ds = db[o] + db[OCn + o] + db[2*OCn + o];
        g_off[o] = (ds - bnm[o]) * sc + bnb[o];
    }
}

// ---------------------------------------------------------------------------
// kB: block = (64-col tile, n), 3 blocks/SM. For each s:
//   GEMM1 (mma tf32): xm[col][c] = sum_v x[c][t,v] * Aad_s[v][w(col)]
//   GEMM2 (mma tf32): D[col][o] += xm[col][c] * W_s[c][o]
// Epilogue: D + off + residual, ReLU.
// ---------------------------------------------------------------------------
__global__ __launch_bounds__(256, 3) void kB(
    const float* __restrict__ x,
    float* __restrict__ out)
{
    extern __shared__ float sm[];
    float* s_x   = sm;                       // [64][108] x as tf32 bits
    float* s_xm  = s_x  + CC*XST;            // [64][68]  tf32 bits
    float* s_w   = s_xm + CT*XMS;            // [64][72]  tf32 bits (per s)
    float* s_Af  = s_w  + CC*WST;            // [96][32]  A_adp frags, tf32
    float* s_off = s_Af + 96*32;             // [64]

    const int tid  = threadIdx.x;
    const int wid  = tid >> 5;
    const int lane = tid & 31;
    const int gr   = lane >> 2;        // 0..7
    const int tc   = lane & 3;         // 0..3
    const int blk  = blockIdx.x;
    const int n    = blockIdx.y;
    const int cbase = blk * CT;
    const int t0    = cbase / VV;
    const int coff  = cbase - t0*VV;   // 0..24

    const float* xn = x + (size_t)n*(CC*NCOL);

    // ---- prologue staging ----
    // x tile as tf32 bits: s_x[c][xc], xc in [0,100); zeros in [100,108)
    for (int idx = tid; idx < CC*100; idx += 256) {
        int c = idx / 100, xc = idx % 100;
        int g = t0*VV + xc;
        float v = (g < NCOL) ? xn[(size_t)c*NCOL + g] : 0.f;
        s_x[c*XST + xc] = __uint_as_float(f2tf32(v));
    }
    for (int idx = tid; idx < CC*8; idx += 256) {
        int c = idx >> 3, p = idx & 7;
        s_x[c*XST + 100 + p] = 0.f;
    }
    // A_adp fragments: s_Af[((s*4+kt)*4+wt)*2+reg][lane]
    for (int idx = tid; idx < 96*32; idx += 256) {
        int lane_i = idx & 31;
        int r      = idx >> 5;
        int reg = r & 1;
        int wt  = (r >> 1) & 3;
        int kt  = (r >> 3) & 3;
        int s   = r >> 5;
        int gri = lane_i >> 2, tci = lane_i & 3;
        int v = kt*8 + tci + reg*4;
        int w = wt*8 + gri;
        float val = (v < VV && w < VV)
                  ? g_Aadp[((size_t)n*SS + s)*(VV*VV) + v*VV + w] : 0.f;
        s_Af[idx] = __uint_as_float(f2tf32(val));
    }
    if (tid < OCn) s_off[tid] = g_off[tid];
    __syncthreads();

    // GEMM1 mapping: warp -> (tl = wid&3, mt = wid>>2 and +2)
    const int tl = wid & 3;
    // GEMM2 mapping: warp -> (ct = wid&3 col quarter, oh = wid>>2)
    const int ctq = wid & 3;
    const int oh  = wid >> 2;

    const uint32_t* xu  = reinterpret_cast<const uint32_t*>(s_x);
    const uint32_t* xmu = reinterpret_cast<const uint32_t*>(s_xm);
    const uint32_t* wu  = reinterpret_cast<const uint32_t*>(s_w);
    const uint32_t* afu = reinterpret_cast<const uint32_t*>(s_Af);
    uint32_t* xmw = reinterpret_cast<uint32_t*>(s_xm);

    float dY[4][4];
    #pragma unroll
    for (int nt = 0; nt < 4; nt++)
        #pragma unroll
        for (int j = 0; j < 4; j++) dY[nt][j] = 0.f;

    for (int s = 0; s < SS; s++) {
        if (s) __syncthreads();   // prior GEMM2 done with s_xm, s_w
        // stage W_s (disjoint from GEMM1's smem traffic)
        for (int idx = tid; idx < CC*OCn; idx += 256) {
            int k = idx >> 6, o = idx & 63;
            s_w[k*WST + o] = g_wdT[s*(CC*OCn) + idx];
        }

        // ---- GEMM1 via mma: D1[c, w] per (tl) ----
        #pragma unroll
        for (int mi = 0; mi < 2; mi++) {
            const int mt = (wid >> 2) + 2*mi;   // 0..3
            const int c0 = mt*16;
            uint32_t a[4][4];
            #pragma unroll
            for (int kt = 0; kt < 4; kt++) {
                int base = (c0 + gr)*XST + tl*VV + kt*8 + tc;
                a[kt][0] = xu[base];
                a[kt][1] = xu[base + 8*XST];
                a[kt][2] = xu[base + 4];
                a[kt][3] = xu[base + 8*XST + 4];
            }
            #pragma unroll
            for (int wt = 0; wt < 4; wt++) {
                float d[4] = {0.f, 0.f, 0.f, 0.f};
                #pragma unroll
                for (int kt = 0; kt < 4; kt++) {
                    int fb = (((s*4 + kt)*4 + wt)*2)*32 + lane;
                    uint32_t b0 = afu[fb];
                    uint32_t b1 = afu[fb + 32];
                    mma_tf32(d, a[kt][0], a[kt][1], a[kt][2], a[kt][3], b0, b1);
                }
                int w0  = wt*8 + 2*tc;
                int lc0 = tl*VV + w0 - coff;
                if (w0 < VV && lc0 >= 0 && lc0 < CT) {
                    xmw[lc0*XMS + c0 + gr]     = f2tf32(d[0]);
                    xmw[lc0*XMS + c0 + gr + 8] = f2tf32(d[2]);
                }
                int w1  = w0 + 1;
                int lc1 = lc0 + 1;
                if (w1 < VV && lc1 >= 0 && lc1 < CT) {
                    xmw[lc1*XMS + c0 + gr]     = f2tf32(d[1]);
                    xmw[lc1*XMS + c0 + gr + 8] = f2tf32(d[3]);
                }
            }
        }
        __syncthreads();

        // ---- GEMM2 via mma: K = 64 (this s) ----
        #pragma unroll 2
        for (int kq = 0; kq < 8; kq++) {
            int k = kq*8;
            uint32_t a0 = xmu[(ctq*16 + gr    )*XMS + k + tc];
            uint32_t a1 = xmu[(ctq*16 + gr + 8)*XMS + k + tc];
            uint32_t a2 = xmu[(ctq*16 + gr    )*XMS + k + tc + 4];
            uint32_t a3 = xmu[(ctq*16 + gr + 8)*XMS + k + tc + 4];
            #pragma unroll
            for (int nt = 0; nt < 4; nt++) {
                int o0 = oh*32 + nt*8;
                uint32_t b0 = wu[(k + tc    )*WST + o0 + gr];
                uint32_t b1 = wu[(k + tc + 4)*WST + o0 + gr];
                mma_tf32(dY[nt], a0, a1, a2, a3, b0, b1);
            }
        }
    }

    // ---- epilogue ----
    {
        const int row0 = ctq*16 + gr;
        const int row1 = row0 + 8;
        const int colg0 = cbase + row0;
        const int colg1 = cbase + row1;
        const bool ok0 = (colg0 < NCOL);
        const bool ok1 = (colg1 < NCOL);
        float* on = out + (size_t)n*(CC*NCOL);
        #pragma unroll
        for (int nt = 0; nt < 4; nt++) {
            int oe = oh*32 + nt*8 + 2*tc;
            int oo = oe + 1;
            float offe = s_off[oe], offo = s_off[oo];
            if (ok0) {
                float v0 = dY[nt][0] + offe + xn[(size_t)oe*NCOL + colg0];
                float v1 = dY[nt][1] + offo + xn[(size_t)oo*NCOL + colg0];
                on[(size_t)oe*NCOL + colg0] = fmaxf(v0, 0.f);
                on[(size_t)oo*NCOL + colg0] = fmaxf(v1, 0.f);
            }
            if (ok1) {
                float v2 = dY[nt][2] + offe + xn[(size_t)oe*NCOL + colg1];
                float v3 = dY[nt][3] + offo + xn[(size_t)oo*NCOL + colg1];
                on[(size_t)oe*NCOL + colg1] = fmaxf(v2, 0.f);
                on[(size_t)oo*NCOL + colg1] = fmaxf(v3, 0.f);
            }
        }
    }
}

// ---------------------------------------------------------------------------
extern "C" void kernel_launch(void* const* d_in, const int* in_sizes, int n_in,
                              void* d_out, int out_size)
{
    const float* x     = (const float*)d_in[0];
    const float* A     = (const float*)d_in[1];
    const float* alpha = (const float*)d_in[2];
    const float* caw   = (const float*)d_in[3];
    const float* cab   = (const float*)d_in[4];
    const float* cbw   = (const float*)d_in[5];
    const float* cbb   = (const float*)d_in[6];
    const float* bag   = (const float*)d_in[7];
    const float* babt  = (const float*)d_in[8];
    const float* bam   = (const float*)d_in[9];
    const float* bav   = (const float*)d_in[10];
    const float* bbg   = (const float*)d_in[11];
    const float* bbbt  = (const float*)d_in[12];
    const float* bbm   = (const float*)d_in[13];
    const float* bbv   = (const float*)d_in[14];
    const float* cdw   = (const float*)d_in[15];
    const float* cdb   = (const float*)d_in[16];
    const float* bng   = (const float*)d_in[17];
    const float* bnb   = (const float*)d_in[18];
    const float* bnm   = (const float*)d_in[19];
    const float* bnv   = (const float*)d_in[20];
    float* out = (float*)d_out;

    const int smemB = (CC*XST + CT*XMS + CC*WST + 96*32 + 64) * sizeof(float);
    cudaFuncSetAttribute(kB, cudaFuncAttributeMaxDynamicSharedMemorySize, smemB);

    kW<<<(SS*OCn*CC + 255)/256, 256>>>(cdw, cdb, bng, bnb, bnm, bnv);
    kConv<<<dim3(NTCB, SS, NN), 256>>>(x, caw, cab, cbw, cbb,
                                       bag, babt, bam, bav,
                                       bbg, bbbt, bbm, bbv);
    kM<<<dim3(NCH, SS, NN), 256>>>();
    kA2<<<(NN*SS*VV*VV + 255)/256, 256>>>(A, alpha);
    kB<<<dim3(NTBL, NN), 256, smemB>>>(x, out);
}

// round 10
// speedup vs baseline: 1.5543x; 1.1245x over previous
#include <cuda_runtime.h>
#include <cuda_bf16.h>
#include <cstdint>

#define EPSF 1e-5f

// Problem dims
#define NN  64
#define CC  64
#define TD  300
#define VV  25
#define SS  3
#define ICn 16
#define OCn 64
#define NCOL (TD*VV)          // 7500

// kConv tiling
#define TCB   20
#define NTCB  (TD/TCB)        // 15
#define COLSB (TCB*VV)        // 500

// kM tiling
#define NCH  5
#define KTOT (ICn*TD)         // 4800
#define KCH  (KTOT/NCH)       // 960
#define KST  64
#define NSTG (KCH/KST)        // 15

// kB tiling
#define CT    64                      // cols per block
#define NTBL  ((NCOL + CT - 1)/CT)    // 118
#define XMS   68                      // xm row stride
#define WST   72                      // W row stride

typedef unsigned long long u64;

__device__ __nv_bfloat162 g_ab[(size_t)NN*SS*KTOT*32];
__device__ float g_Mpart[NCH*NN*SS*VV*VV];
__device__ float g_Aadp [NN*SS*VV*VV];
__device__ float g_wdT  [SS*CC*OCn];   // [s][c][o], BN-scaled, tf32 bits
__device__ float g_off  [OCn];

__device__ __forceinline__ float tanh_fast(float x) {
    float y;
    asm("tanh.approx.f32 %0, %1;" : "=f"(y) : "f"(x));
    return y;
}
__device__ __forceinline__ u64 pack2(float lo, float hi) {
    u64 r; asm("mov.b64 %0, {%1, %2};" : "=l"(r) : "f"(lo), "f"(hi)); return r;
}
__device__ __forceinline__ float2 unpack2(u64 p) {
    float2 r; asm("mov.b64 {%0, %1}, %2;" : "=f"(r.x), "=f"(r.y) : "l"(p)); return r;
}
__device__ __forceinline__ void fma2(u64& d, u64 a, u64 b) {
    asm("fma.rn.f32x2 %0, %1, %2, %0;" : "+l"(d) : "l"(a), "l"(b));
}
__device__ __forceinline__ uint32_t f2tf32(float x) {
    uint32_t u;
    asm("cvt.rna.tf32.f32 %0, %1;" : "=r"(u) : "f"(x));
    return u;
}
__device__ __forceinline__ void mma_tf32(float d[4],
    uint32_t a0, uint32_t a1, uint32_t a2, uint32_t a3,
    uint32_t b0, uint32_t b1)
{
    asm volatile(
        "mma.sync.aligned.m16n8k8.row.col.f32.tf32.tf32.f32 "
        "{%0,%1,%2,%3}, {%4,%5,%6,%7}, {%8,%9}, {%0,%1,%2,%3};\n"
        : "+f"(d[0]), "+f"(d[1]), "+f"(d[2]), "+f"(d[3])
        : "r"(a0), "r"(a1), "r"(a2), "r"(a3), "r"(b0), "r"(b1));
}

// ---------------------------------------------------------------------------
// kConv: a = tanh(bn(Wa x)), b = tanh(bn(Wb x)) -> g_ab (bf16 pairs).
// ---------------------------------------------------------------------------
__global__ __launch_bounds__(256) void kConv(
    const float* __restrict__ x,
    const float* __restrict__ wa, const float* __restrict__ ba,
    const float* __restrict__ wb, const float* __restrict__ bb,
    const float* __restrict__ gag, const float* __restrict__ gab,
    const float* __restrict__ gam, const float* __restrict__ gav,
    const float* __restrict__ gbg, const float* __restrict__ gbb,
    const float* __restrict__ gbm, const float* __restrict__ gbv)
{
    __shared__ __align__(16) float s_w[CC*32];
    __shared__ float s_sha[ICn], s_shb[ICn];

    const int tid = threadIdx.x;
    const int tc  = blockIdx.x;
    const int s   = blockIdx.y;
    const int n   = blockIdx.z;

    for (int idx = tid; idx < ICn*CC; idx += 256) {
        int i = idx / CC, c = idx % CC;
        float sca = gag[s*ICn+i] * rsqrtf(gav[s*ICn+i] + EPSF);
        float scb = gbg[s*ICn+i] * rsqrtf(gbv[s*ICn+i] + EPSF);
        s_w[c*32 + i]      = wa[s*ICn*CC + idx] * sca;
        s_w[c*32 + 16 + i] = wb[s*ICn*CC + idx] * scb;
    }
    if (tid < ICn) {
        float sca = gag[s*ICn+tid] * rsqrtf(gav[s*ICn+tid] + EPSF);
        float scb = gbg[s*ICn+tid] * rsqrtf(gbv[s*ICn+tid] + EPSF);
        s_sha[tid] = (ba[s*ICn+tid] - gam[s*ICn+tid]) * sca + gab[s*ICn+tid];
        s_shb[tid] = (bb[s*ICn+tid] - gbm[s*ICn+tid]) * scb + gbb[s*ICn+tid];
    }
    __syncthreads();
    if (tid >= COLSB/2) return;

    const int col0 = tc*COLSB + 2*tid;
    const int col1 = col0 + 1;
    const int t0 = col0 / 25, v0 = col0 - 25*t0;
    const int t1 = col1 / 25, v1 = col1 - 25*t1;

    u64 accA0[8], accA1[8], accB0[8], accB1[8];
    #pragma unroll
    for (int p = 0; p < 8; p++) {
        u64 ia = pack2(s_sha[2*p], s_sha[2*p+1]);
        u64 ib = pack2(s_shb[2*p], s_shb[2*p+1]);
        accA0[p] = ia; accA1[p] = ia;
        accB0[p] = ib; accB1[p] = ib;
    }

    const float* xp = x + (size_t)n*(CC*NCOL) + col0;
    #pragma unroll 4
    for (int c = 0; c < CC; c++) {
        float2 xv = *reinterpret_cast<const float2*>(xp + (size_t)c*NCOL);
        u64 xd0 = pack2(xv.x, xv.x);
        u64 xd1 = pack2(xv.y, xv.y);
        const ulonglong2* wrow = reinterpret_cast<const ulonglong2*>(&s_w[c*32]);
        #pragma unroll
        for (int g = 0; g < 4; g++) {
            ulonglong2 w2 = wrow[g];
            fma2(accA0[2*g],   w2.x, xd0); fma2(accA1[2*g],   w2.x, xd1);
            fma2(accA0[2*g+1], w2.y, xd0); fma2(accA1[2*g+1], w2.y, xd1);
        }
        #pragma unroll
        for (int g = 0; g < 4; g++) {
            ulonglong2 w2 = wrow[4+g];
            fma2(accB0[2*g],   w2.x, xd0); fma2(accB1[2*g],   w2.x, xd1);
            fma2(accB0[2*g+1], w2.y, xd0); fma2(accB1[2*g+1], w2.y, xd1);
        }
    }

    __nv_bfloat162* gb = g_ab + (size_t)(n*SS + s)*KTOT*32;
    #pragma unroll
    for (int p = 0; p < 8; p++) {
        float2 a0 = unpack2(accA0[p]);
        float2 b0 = unpack2(accB0[p]);
        float2 a1 = unpack2(accA1[p]);
        float2 b1 = unpack2(accB1[p]);
        __nv_bfloat162 h;
        h.x = __float2bfloat16(tanh_fast(a0.x));
        h.y = __float2bfloat16(tanh_fast(b0.x));
        gb[(size_t)(t0*ICn + 2*p)*32 + v0] = h;
        h.x = __float2bfloat16(tanh_fast(a0.y));
        h.y = __float2bfloat16(tanh_fast(b0.y));
        gb[(size_t)(t0*ICn + 2*p+1)*32 + v0] = h;
        h.x = __float2bfloat16(tanh_fast(a1.x));
        h.y = __float2bfloat16(tanh_fast(b1.x));
        gb[(size_t)(t1*ICn + 2*p)*32 + v1] = h;
        h.x = __float2bfloat16(tanh_fast(a1.y));
        h.y = __float2bfloat16(tanh_fast(b1.y));
        gb[(size_t)(t1*ICn + 2*p+1)*32 + v1] = h;
    }
}

// ---------------------------------------------------------------------------
// kM: partial M over 960 rows.
// ---------------------------------------------------------------------------
__global__ __launch_bounds__(256) void kM()
{
    __shared__ __align__(16) float s_a32[KST*32];
    __shared__ __align__(16) float s_b32[KST*32];

    const int tid  = threadIdx.x;
    const int wid  = tid >> 5;
    const int lane = tid & 31;
    const int chunk = blockIdx.x;
    const int s     = blockIdx.y;
    const int n     = blockIdx.z;

    const uint4* gsrc = reinterpret_cast<const uint4*>(
        g_ab + ((size_t)(n*SS + s)*KTOT + (size_t)chunk*KCH)*32);

    u64 macc[2] = {0ull, 0ull};

    for (int st = 0; st < NSTG; st++) {
        __syncthreads();
        #pragma unroll
        for (int rep = 0; rep < 2; rep++) {
            int u = tid + rep*256;
            uint4 val = gsrc[st*512 + u];
            int row = u >> 3, q = u & 7;
            float* pa = &s_a32[row*32 + q*4];
            float* pb = &s_b32[row*32 + q*4];
            float2 f0 = __bfloat1622float2(*reinterpret_cast<__nv_bfloat162*>(&val.x));
            float2 f1 = __bfloat1622float2(*reinterpret_cast<__nv_bfloat162*>(&val.y));
            float2 f2 = __bfloat1622float2(*reinterpret_cast<__nv_bfloat162*>(&val.z));
            float2 f3 = __bfloat1622float2(*reinterpret_cast<__nv_bfloat162*>(&val.w));
            pa[0] = f0.x; pb[0] = f0.y;
            pa[1] = f1.x; pb[1] = f1.y;
            pa[2] = f2.x; pb[2] = f2.y;
            pa[3] = f3.x; pb[3] = f3.y;
        }
        __syncthreads();
        #pragma unroll 8
        for (int kk = 0; kk < KST; kk++) {
            float av = s_a32[kk*32 + lane];
            u64 ap = pack2(av, av);
            ulonglong2 bv = *reinterpret_cast<const ulonglong2*>(
                &s_b32[kk*32 + wid*4]);
            fma2(macc[0], ap, bv.x);
            fma2(macc[1], ap, bv.y);
        }
    }

    if (lane < VV) {
        float* mp = &g_Mpart[((size_t)chunk*NN*SS + (size_t)n*SS + s)*(VV*VV)];
        float2 m0 = unpack2(macc[0]);
        float2 m1 = unpack2(macc[1]);
        int w = wid*4;
        if (w   < VV) mp[lane*VV + w]   = m0.x;
        if (w+1 < VV) mp[lane*VV + w+1] = m0.y;
        if (w+2 < VV) mp[lane*VV + w+2] = m1.x;
        if (w+3 < VV) mp[lane*VV + w+3] = m1.y;
    }
}

// ---------------------------------------------------------------------------
// kA2: reduce partials, A_adp = A + tanh(M/(IC*T)) * alpha
// ---------------------------------------------------------------------------
__global__ void kA2(const float* __restrict__ A, const float* __restrict__ alpha)
{
    int idx = blockIdx.x * 256 + threadIdx.x;
    if (idx >= NN*SS*VV*VV) return;
    float m = 0.f;
    #pragma unroll
    for (int ch = 0; ch < NCH; ch++)
        m += g_Mpart[ch*(NN*SS*VV*VV) + idx];
    g_Aadp[idx] = A[idx % (SS*VV*VV)]
                + tanhf(m * (1.f/(float)(ICn*TD))) * alpha[0];
}

// ---------------------------------------------------------------------------
// kW: W -> [s][c][o], BN scale folded, tf32-rounded. g_off.
// ---------------------------------------------------------------------------
__global__ void kW(const float* __restrict__ wd, const float* __restrict__ db,
                   const float* __restrict__ bng, const float* __restrict__ bnb,
                   const float* __restrict__ bnm, const float* __restrict__ bnv)
{
    int idx = blockIdx.x * 256 + threadIdx.x;
    if (idx < SS*OCn*CC) {
        int c = idx & 63;
        int o = (idx >> 6) & 63;
        int s = idx >> 12;
        float sc = bng[o] * rsqrtf(bnv[o] + EPSF);
        uint32_t t = f2tf32(wd[idx] * sc);
        g_wdT[s*(CC*OCn) + c*OCn + o] = __uint_as_float(t);
    }
    if (blockIdx.x == 0 && threadIdx.x < OCn) {
        int o = threadIdx.x;
        float sc = bng[o] * rsqrtf(bnv[o] + EPSF);
        float ds = db[o] + db[OCn + o] + db[2*OCn + o];
        g_off[o] = (ds - bnm[o]) * sc + bnb[o];
    }
}

// ---------------------------------------------------------------------------
// kB: block = (64-col tile, n), 4 blocks/SM. x A-fragments live in registers
// (loaded once from gmem, s-invariant). For each s:
//   GEMM1 (mma tf32): xm[col][c] = sum_v x[c][t,v] * Aad_s[v][w(col)]
//   GEMM2 (mma tf32): D[col][o] += xm[col][c] * W_s[c][o]
// Epilogue: D + off + residual, ReLU.
// ---------------------------------------------------------------------------
__global__ __launch_bounds__(256, 4) void kB(
    const float* __restrict__ x,
    float* __restrict__ out)
{
    extern __shared__ float sm[];
    float* s_xm  = sm;                  // [64][68]  tf32 bits
    float* s_w   = s_xm + CT*XMS;       // [64][72]  tf32 bits (per s)
    float* s_Af  = s_w  + CC*WST;       // [96][32]  A_adp frags, tf32
    float* s_off = s_Af + 96*32;        // [64]

    const int tid  = threadIdx.x;
    const int wid  = tid >> 5;
    const int lane = tid & 31;
    const int gr   = lane >> 2;        // 0..7
    const int tc   = lane & 3;         // 0..3
    const int blk  = blockIdx.x;
    const int n    = blockIdx.y;
    const int cbase = blk * CT;
    const int t0    = cbase / VV;
    const int coff  = cbase - t0*VV;   // 0..24

    const float* xn = x + (size_t)n*(CC*NCOL);

    // ---- prologue staging ----
    // A_adp fragments: s_Af[((s*4+kt)*4+wt)*2+reg][lane]
    for (int idx = tid; idx < 96*32; idx += 256) {
        int lane_i = idx & 31;
        int r      = idx >> 5;
        int reg = r & 1;
        int wt  = (r >> 1) & 3;
        int kt  = (r >> 3) & 3;
        int s   = r >> 5;
        int gri = lane_i >> 2, tci = lane_i & 3;
        int v = kt*8 + tci + reg*4;
        int w = wt*8 + gri;
        float val = (v < VV && w < VV)
                  ? g_Aadp[((size_t)n*SS + s)*(VV*VV) + v*VV + w] : 0.f;
        s_Af[idx] = __uint_as_float(f2tf32(val));
    }
    if (tid < OCn) s_off[tid] = g_off[tid];

    // warp roles
    const int tl = wid & 3;            // GEMM1 t within tile
    const int oh = wid >> 2;           // GEMM1 m-half / GEMM2 o-half
    const int ctq = wid & 3;           // GEMM2 col quarter

    // x A-fragments in registers (s-invariant; rows = c, cols = v)
    uint32_t ax[2][4][4];
    {
        const int colB = (t0 + tl)*VV;
        #pragma unroll
        for (int mi = 0; mi < 2; mi++) {
            const int r0 = (oh + 2*mi)*16 + gr;
            const float* b0p = xn + (size_t)r0*NCOL;
            const float* b1p = b0p + (size_t)8*NCOL;
            #pragma unroll
            for (int kt = 0; kt < 4; kt++) {
                int c0i = colB + kt*8 + tc;
                int c1i = c0i + 4;
                bool k0 = (c0i < NCOL);
                bool k1 = (c1i < NCOL);
                ax[mi][kt][0] = f2tf32(k0 ? b0p[c0i] : 0.f);
                ax[mi][kt][1] = f2tf32(k0 ? b1p[c0i] : 0.f);
                ax[mi][kt][2] = f2tf32(k1 ? b0p[c1i] : 0.f);
                ax[mi][kt][3] = f2tf32(k1 ? b1p[c1i] : 0.f);
            }
        }
    }
    __syncthreads();   // s_Af ready

    const uint32_t* xmu = reinterpret_cast<const uint32_t*>(s_xm);
    const uint32_t* wu  = reinterpret_cast<const uint32_t*>(s_w);
    const uint32_t* afu = reinterpret_cast<const uint32_t*>(s_Af);
    uint32_t* xmw = reinterpret_cast<uint32_t*>(s_xm);

    float dY[4][4];
    #pragma unroll
    for (int nt = 0; nt < 4; nt++)
        #pragma unroll
        for (int j = 0; j < 4; j++) dY[nt][j] = 0.f;

    for (int s = 0; s < SS; s++) {
        if (s) __syncthreads();   // prior GEMM2 done with s_xm, s_w
        // stage W_s (float4 coalesced; overlaps with GEMM1 below)
        {
            const float4* wg = reinterpret_cast<const float4*>(
                g_wdT + s*(CC*OCn));
            for (int idx = tid; idx < CC*OCn/4; idx += 256) {
                int k = idx >> 4, o4 = (idx & 15) << 2;
                *reinterpret_cast<float4*>(&s_w[k*WST + o4]) = wg[idx];
            }
        }

        // ---- GEMM1 via mma: xm[col][c] from reg-resident x frags ----
        #pragma unroll
        for (int mi = 0; mi < 2; mi++) {
            const int c0 = (oh + 2*mi)*16;
            #pragma unroll
            for (int wt = 0; wt < 4; wt++) {
                float d[4] = {0.f, 0.f, 0.f, 0.f};
                #pragma unroll
                for (int kt = 0; kt < 4; kt++) {
                    int fb = (((s*4 + kt)*4 + wt)*2)*32 + lane;
                    mma_tf32(d, ax[mi][kt][0], ax[mi][kt][1],
                                ax[mi][kt][2], ax[mi][kt][3],
                                afu[fb], afu[fb + 32]);
                }
                int w0  = wt*8 + 2*tc;
                int lc0 = tl*VV + w0 - coff;
                if (w0 < VV && lc0 >= 0 && lc0 < CT) {
                    xmw[lc0*XMS + c0 + gr]     = f2tf32(d[0]);
                    xmw[lc0*XMS + c0 + gr + 8] = f2tf32(d[2]);
                }
                int w1  = w0 + 1;
                int lc1 = lc0 + 1;
                if (w1 < VV && lc1 >= 0 && lc1 < CT) {
                    xmw[lc1*XMS + c0 + gr]     = f2tf32(d[1]);
                    xmw[lc1*XMS + c0 + gr + 8] = f2tf32(d[3]);
                }
            }
        }
        __syncthreads();

        // ---- GEMM2 via mma: K = 64 (this s) ----
        #pragma unroll 2
        for (int kq = 0; kq < 8; kq++) {
            int k = kq*8;
            uint32_t a0 = xmu[(ctq*16 + gr    )*XMS + k + tc];
            uint32_t a1 = xmu[(ctq*16 + gr + 8)*XMS + k + tc];
            uint32_t a2 = xmu[(ctq*16 + gr    )*XMS + k + tc + 4];
            uint32_t a3 = xmu[(ctq*16 + gr + 8)*XMS + k + tc + 4];
            #pragma unroll
            for (int nt = 0; nt < 4; nt++) {
                int o0 = oh*32 + nt*8;
                uint32_t b0 = wu[(k + tc    )*WST + o0 + gr];
                uint32_t b1 = wu[(k + tc + 4)*WST + o0 + gr];
                mma_tf32(dY[nt], a0, a1, a2, a3, b0, b1);
            }
        }
    }

    // ---- epilogue ----
    {
        const int row0 = ctq*16 + gr;
        const int row1 = row0 + 8;
        const int colg0 = cbase + row0;
        const int colg1 = cbase + row1;
        const bool ok0 = (colg0 < NCOL);
        const bool ok1 = (colg1 < NCOL);
        float* on = out + (size_t)n*(CC*NCOL);
        #pragma unroll
        for (int nt = 0; nt < 4; nt++) {
            int oe = oh*32 + nt*8 + 2*tc;
            int oo = oe + 1;
            float offe = s_off[oe], offo = s_off[oo];
            if (ok0) {
                float v0 = dY[nt][0] + offe + xn[(size_t)oe*NCOL + colg0];
                float v1 = dY[nt][1] + offo + xn[(size_t)oo*NCOL + colg0];
                on[(size_t)oe*NCOL + colg0] = fmaxf(v0, 0.f);
                on[(size_t)oo*NCOL + colg0] = fmaxf(v1, 0.f);
            }
            if (ok1) {
                float v2 = dY[nt][2] + offe + xn[(size_t)oe*NCOL + colg1];
                float v3 = dY[nt][3] + offo + xn[(size_t)oo*NCOL + colg1];
                on[(size_t)oe*NCOL + colg1] = fmaxf(v2, 0.f);
                on[(size_t)oo*NCOL + colg1] = fmaxf(v3, 0.f);
            }
        }
    }
}

// ---------------------------------------------------------------------------
extern "C" void kernel_launch(void* const* d_in, const int* in_sizes, int n_in,
                              void* d_out, int out_size)
{
    const float* x     = (const float*)d_in[0];
    const float* A     = (const float*)d_in[1];
    const float* alpha = (const float*)d_in[2];
    const float* caw   = (const float*)d_in[3];
    const float* cab   = (const float*)d_in[4];
    const float* cbw   = (const float*)d_in[5];
    const float* cbb   = (const float*)d_in[6];
    const float* bag   = (const float*)d_in[7];
    const float* babt  = (const float*)d_in[8];
    const float* bam   = (const float*)d_in[9];
    const float* bav   = (const float*)d_in[10];
    const float* bbg   = (const float*)d_in[11];
    const float* bbbt  = (const float*)d_in[12];
    const float* bbm   = (const float*)d_in[13];
    const float* bbv   = (const float*)d_in[14];
    const float* cdw   = (const float*)d_in[15];
    const float* cdb   = (const float*)d_in[16];
    const float* bng   = (const float*)d_in[17];
    const float* bnb   = (const float*)d_in[18];
    const float* bnm   = (const float*)d_in[19];
    const float* bnv   = (const float*)d_in[20];
    float* out = (float*)d_out;

    const int smemB = (CT*XMS + CC*WST + 96*32 + 64) * sizeof(float);
    cudaFuncSetAttribute(kB, cudaFuncAttributeMaxDynamicSharedMemorySize, smemB);

    kW<<<(SS*OCn*CC + 255)/256, 256>>>(cdw, cdb, bng, bnb, bnm, bnv);
    kConv<<<dim3(NTCB, SS, NN), 256>>>(x, caw, cab, cbw, cbb,
                                       bag, babt, bam, bav,
                                       bbg, bbbt, bbm, bbv);
    kM<<<dim3(NCH, SS, NN), 256>>>();
    kA2<<<(NN*SS*VV*VV + 255)/256, 256>>>(A, alpha);
    kB<<<dim3(NTBL, NN), 256, smemB>>>(x, out);
}

// round 11
// speedup vs baseline: 1.7445x; 1.1224x over previous
#include <cuda_runtime.h>
#include <cuda_bf16.h>
#include <cstdint>

#define EPSF 1e-5f

// Problem dims
#define NN  64
#define CC  64
#define TD  300
#define VV  25
#define SS  3
#define ICn 16
#define OCn 64
#define NCOL (TD*VV)          // 7500

// kConv tiling
#define TCB   20
#define NTCB  (TD/TCB)        // 15
#define COLSB (TCB*VV)        // 500

// kM tiling
#define NCH  5
#define KTOT (ICn*TD)         // 4800
#define KCH  (KTOT/NCH)       // 960
#define KST  64
#define NSTG (KCH/KST)        // 15

// kB tiling
#define CT    64                      // cols per block
#define NTBL  ((NCOL + CT - 1)/CT)    // 118
#define XMS   68                      // xm row stride
#define WST   72                      // W row stride

typedef unsigned long long u64;

__device__ __nv_bfloat162 g_ab[(size_t)NN*SS*KTOT*32];
__device__ float g_Mpart[NCH*NN*SS*VV*VV];
__device__ float g_Aadp [NN*SS*VV*VV];
__device__ float g_wdT  [SS*CC*OCn];   // [s][c][o], BN-scaled, tf32 bits
__device__ float g_off  [OCn];

__device__ __forceinline__ float tanh_fast(float x) {
    float y;
    asm("tanh.approx.f32 %0, %1;" : "=f"(y) : "f"(x));
    return y;
}
__device__ __forceinline__ u64 pack2(float lo, float hi) {
    u64 r; asm("mov.b64 %0, {%1, %2};" : "=l"(r) : "f"(lo), "f"(hi)); return r;
}
__device__ __forceinline__ float2 unpack2(u64 p) {
    float2 r; asm("mov.b64 {%0, %1}, %2;" : "=f"(r.x), "=f"(r.y) : "l"(p)); return r;
}
__device__ __forceinline__ void fma2(u64& d, u64 a, u64 b) {
    asm("fma.rn.f32x2 %0, %1, %2, %0;" : "+l"(d) : "l"(a), "l"(b));
}
__device__ __forceinline__ uint32_t f2tf32(float x) {
    uint32_t u;
    asm("cvt.rna.tf32.f32 %0, %1;" : "=r"(u) : "f"(x));
    return u;
}
__device__ __forceinline__ void mma_tf32(float d[4],
    uint32_t a0, uint32_t a1, uint32_t a2, uint32_t a3,
    uint32_t b0, uint32_t b1)
{
    asm volatile(
        "mma.sync.aligned.m16n8k8.row.col.f32.tf32.tf32.f32 "
        "{%0,%1,%2,%3}, {%4,%5,%6,%7}, {%8,%9}, {%0,%1,%2,%3};\n"
        : "+f"(d[0]), "+f"(d[1]), "+f"(d[2]), "+f"(d[3])
        : "r"(a0), "r"(a1), "r"(a2), "r"(a3), "r"(b0), "r"(b1));
}

// ---------------------------------------------------------------------------
// kConv (tensor-core): per (chunk, s, n):
//   D[io][col] = sum_c Wab[io][c] * x[c][col]   (io: 0..15 = a, 16..31 = b)
//   out = tanh(D + shift) -> g_ab bf16 pairs. No barriers in main loop.
// A-frags (weights) reg-resident; B-frags loaded straight from gmem.
// ---------------------------------------------------------------------------
__global__ __launch_bounds__(256, 2) void kConv(
    const float* __restrict__ x,
    const float* __restrict__ wa, const float* __restrict__ ba,
    const float* __restrict__ wb, const float* __restrict__ bb,
    const float* __restrict__ gag, const float* __restrict__ gab,
    const float* __restrict__ gam, const float* __restrict__ gav,
    const float* __restrict__ gbg, const float* __restrict__ gbb,
    const float* __restrict__ gbm, const float* __restrict__ gbv)
{
    __shared__ __align__(16) float s_wf[32*68];   // [io][c] tf32 bits
    __shared__ float s_sh[32];                    // shifts: a 0..15, b 16..31

    const int tid  = threadIdx.x;
    const int wid  = tid >> 5;
    const int lane = tid & 31;
    const int gr   = lane >> 2;        // 0..7
    const int tc   = lane & 3;         // 0..3
    const int chunk = blockIdx.x;
    const int s     = blockIdx.y;
    const int n     = blockIdx.z;

    // Fold BN into weights (tf32) and shifts
    for (int idx = tid; idx < 32*CC; idx += 256) {
        int io = idx >> 6, c = idx & 63;
        int i  = io & 15;
        bool isB = io >= 16;
        float g  = isB ? gbg[s*ICn+i] : gag[s*ICn+i];
        float vv = isB ? gbv[s*ICn+i] : gav[s*ICn+i];
        float wv = isB ? wb[s*ICn*CC + i*CC + c] : wa[s*ICn*CC + i*CC + c];
        float sc = g * rsqrtf(vv + EPSF);
        s_wf[io*68 + c] = __uint_as_float(f2tf32(wv * sc));
    }
    if (tid < 32) {
        int i = tid & 15;
        bool isB = tid >= 16;
        float g  = isB ? gbg[s*ICn+i] : gag[s*ICn+i];
        float vv = isB ? gbv[s*ICn+i] : gav[s*ICn+i];
        float bs = isB ? bb[s*ICn+i]  : ba[s*ICn+i];
        float mn = isB ? gbm[s*ICn+i] : gam[s*ICn+i];
        float bt = isB ? gbb[s*ICn+i] : gab[s*ICn+i];
        float sc = g * rsqrtf(vv + EPSF);
        s_sh[tid] = (bs - mn) * sc + bt;
    }
    __syncthreads();

    // Hoist all A fragments (weights): 2 m-tiles x 8 k-tiles x 4 regs
    const uint32_t* wfu = reinterpret_cast<const uint32_t*>(s_wf);
    uint32_t af[2][8][4];
    #pragma unroll
    for (int mi = 0; mi < 2; mi++)
        #pragma unroll
        for (int kt = 0; kt < 8; kt++) {
            int r0 = (mi*16 + gr)*68 + kt*8 + tc;
            af[mi][kt][0] = wfu[r0];
            af[mi][kt][1] = wfu[r0 + 8*68];
            af[mi][kt][2] = wfu[r0 + 4];
            af[mi][kt][3] = wfu[r0 + 8*68 + 4];
        }
    const float sha0 = s_sh[gr],      sha8 = s_sh[gr + 8];
    const float shb0 = s_sh[16 + gr], shb8 = s_sh[24 + gr];

    const float* xn = x + (size_t)n*(CC*NCOL);
    __nv_bfloat162* gb = g_ab + (size_t)(n*SS + s)*KTOT*32;

    const int lwbase = wid*64;             // warp's local col base (0..448)

    #pragma unroll 2
    for (int nt = 0; nt < 8; nt++) {
        const int n0 = nt*8;
        const int lcol = lwbase + n0 + gr;               // local col this lane
        const bool ld  = (lcol < COLSB);
        const int colg = chunk*COLSB + lcol;

        // B fragments from gmem (x[c][colg]); zeros in pad region
        uint32_t bf[8][2];
        const float* xp = xn + colg;
        #pragma unroll
        for (int kt = 0; kt < 8; kt++) {
            float v0 = ld ? xp[(size_t)(kt*8 + tc)*NCOL]     : 0.f;
            float v1 = ld ? xp[(size_t)(kt*8 + tc + 4)*NCOL] : 0.f;
            bf[kt][0] = f2tf32(v0);
            bf[kt][1] = f2tf32(v1);
        }

        float da[4] = {0.f, 0.f, 0.f, 0.f};   // a rows (io 0..15)
        float dbv[4] = {0.f, 0.f, 0.f, 0.f};  // b rows (io 16..31)
        #pragma unroll
        for (int kt = 0; kt < 8; kt++) {
            mma_tf32(da,  af[0][kt][0], af[0][kt][1], af[0][kt][2], af[0][kt][3],
                     bf[kt][0], bf[kt][1]);
            mma_tf32(dbv, af[1][kt][0], af[1][kt][1], af[1][kt][2], af[1][kt][3],
                     bf[kt][0], bf[kt][1]);
        }

        // tanh + pack + scatter-store
        float a0 = tanh_fast(da[0] + sha0);
        float a1 = tanh_fast(da[1] + sha0);
        float a2 = tanh_fast(da[2] + sha8);
        float a3 = tanh_fast(da[3] + sha8);
        float b0 = tanh_fast(dbv[0] + shb0);
        float b1 = tanh_fast(dbv[1] + shb0);
        float b2 = tanh_fast(dbv[2] + shb8);
        float b3 = tanh_fast(dbv[3] + shb8);

        const int lc0 = lwbase + n0 + 2*tc;
        if (lc0 < COLSB) {
            int gc = chunk*COLSB + lc0;
            int t = gc / 25, v = gc - 25*t;
            __nv_bfloat162 h0; h0.x = __float2bfloat16(a0); h0.y = __float2bfloat16(b0);
            __nv_bfloat162 h2; h2.x = __float2bfloat16(a2); h2.y = __float2bfloat16(b2);
            gb[(size_t)(t*ICn + gr)*32 + v]     = h0;
            gb[(size_t)(t*ICn + gr + 8)*32 + v] = h2;
        }
        if (lc0 + 1 < COLSB) {
            int gc = chunk*COLSB + lc0 + 1;
            int t = gc / 25, v = gc - 25*t;
            __nv_bfloat162 h1; h1.x = __float2bfloat16(a1); h1.y = __float2bfloat16(b1);
            __nv_bfloat162 h3; h3.x = __float2bfloat16(a3); h3.y = __float2bfloat16(b3);
            gb[(size_t)(t*ICn + gr)*32 + v]     = h1;
            gb[(size_t)(t*ICn + gr + 8)*32 + v] = h3;
        }
    }
}

// ---------------------------------------------------------------------------
// kM: partial M over 960 rows.
// ---------------------------------------------------------------------------
__global__ __launch_bounds__(256) void kM()
{
    __shared__ __align__(16) float s_a32[KST*32];
    __shared__ __align__(16) float s_b32[KST*32];

    const int tid  = threadIdx.x;
    const int wid  = tid >> 5;
    const int lane = tid & 31;
    const int chunk = blockIdx.x;
    const int s     = blockIdx.y;
    const int n     = blockIdx.z;

    const uint4* gsrc = reinterpret_cast<const uint4*>(
        g_ab + ((size_t)(n*SS + s)*KTOT + (size_t)chunk*KCH)*32);

    u64 macc[2] = {0ull, 0ull};

    for (int st = 0; st < NSTG; st++) {
        __syncthreads();
        #pragma unroll
        for (int rep = 0; rep < 2; rep++) {
            int u = tid + rep*256;
            uint4 val = gsrc[st*512 + u];
            int row = u >> 3, q = u & 7;
            float* pa = &s_a32[row*32 + q*4];
            float* pb = &s_b32[row*32 + q*4];
            float2 f0 = __bfloat1622float2(*reinterpret_cast<__nv_bfloat162*>(&val.x));
            float2 f1 = __bfloat1622float2(*reinterpret_cast<__nv_bfloat162*>(&val.y));
            float2 f2 = __bfloat1622float2(*reinterpret_cast<__nv_bfloat162*>(&val.z));
            float2 f3 = __bfloat1622float2(*reinterpret_cast<__nv_bfloat162*>(&val.w));
            pa[0] = f0.x; pb[0] = f0.y;
            pa[1] = f1.x; pb[1] = f1.y;
            pa[2] = f2.x; pb[2] = f2.y;
            pa[3] = f3.x; pb[3] = f3.y;
        }
        __syncthreads();
        #pragma unroll 8
        for (int kk = 0; kk < KST; kk++) {
            float av = s_a32[kk*32 + lane];
            u64 ap = pack2(av, av);
            ulonglong2 bv = *reinterpret_cast<const ulonglong2*>(
                &s_b32[kk*32 + wid*4]);
            fma2(macc[0], ap, bv.x);
            fma2(macc[1], ap, bv.y);
        }
    }

    if (lane < VV) {
        float* mp = &g_Mpart[((size_t)chunk*NN*SS + (size_t)n*SS + s)*(VV*VV)];
        float2 m0 = unpack2(macc[0]);
        float2 m1 = unpack2(macc[1]);
        int w = wid*4;
        if (w   < VV) mp[lane*VV + w]   = m0.x;
        if (w+1 < VV) mp[lane*VV + w+1] = m0.y;
        if (w+2 < VV) mp[lane*VV + w+2] = m1.x;
        if (w+3 < VV) mp[lane*VV + w+3] = m1.y;
    }
}

// ---------------------------------------------------------------------------
// kA2: reduce partials, A_adp = A + tanh(M/(IC*T)) * alpha
// ---------------------------------------------------------------------------
__global__ void kA2(const float* __restrict__ A, const float* __restrict__ alpha)
{
    int idx = blockIdx.x * 256 + threadIdx.x;
    if (idx >= NN*SS*VV*VV) return;
    float m = 0.f;
    #pragma unroll
    for (int ch = 0; ch < NCH; ch++)
        m += g_Mpart[ch*(NN*SS*VV*VV) + idx];
    g_Aadp[idx] = A[idx % (SS*VV*VV)]
                + tanhf(m * (1.f/(float)(ICn*TD))) * alpha[0];
}

// ---------------------------------------------------------------------------
// kW: W -> [s][c][o], BN scale folded, tf32-rounded. g_off.
// ---------------------------------------------------------------------------
__global__ void kW(const float* __restrict__ wd, const float* __restrict__ db,
                   const float* __restrict__ bng, const float* __restrict__ bnb,
                   const float* __restrict__ bnm, const float* __restrict__ bnv)
{
    int idx = blockIdx.x * 256 + threadIdx.x;
    if (idx < SS*OCn*CC) {
        int c = idx & 63;
        int o = (idx >> 6) & 63;
        int s = idx >> 12;
        float sc = bng[o] * rsqrtf(bnv[o] + EPSF);
        uint32_t t = f2tf32(wd[idx] * sc);
        g_wdT[s*(CC*OCn) + c*OCn + o] = __uint_as_float(t);
    }
    if (blockIdx.x == 0 && threadIdx.x < OCn) {
        int o = threadIdx.x;
        float sc = bng[o] * rsqrtf(bnv[o] + EPSF);
        float ds = db[o] + db[OCn + o] + db[2*OCn + o];
        g_off[o] = (ds - bnm[o]) * sc + bnb[o];
    }
}

// ---------------------------------------------------------------------------
// kB: block = (64-col tile, n), 4 blocks/SM. x A-fragments live in registers
// (loaded once from gmem, s-invariant). For each s:
//   GEMM1 (mma tf32): xm[col][c] = sum_v x[c][t,v] * Aad_s[v][w(col)]
//   GEMM2 (mma tf32): D[col][o] += xm[col][c] * W_s[c][o]
// Epilogue: D + off + residual, ReLU.
// ---------------------------------------------------------------------------
__global__ __launch_bounds__(256, 4) void kB(
    const float* __restrict__ x,
    float* __restrict__ out)
{
    extern __shared__ float sm[];
    float* s_xm  = sm;                  // [64][68]  tf32 bits
    float* s_w   = s_xm + CT*XMS;       // [64][72]  tf32 bits (per s)
    float* s_Af  = s_w  + CC*WST;       // [96][32]  A_adp frags, tf32
    float* s_off = s_Af + 96*32;        // [64]

    const int tid  = threadIdx.x;
    const int wid  = tid >> 5;
    const int lane = tid & 31;
    const int gr   = lane >> 2;        // 0..7
    const int tc   = lane & 3;         // 0..3
    const int blk  = blockIdx.x;
    const int n    = blockIdx.y;
    const int cbase = blk * CT;
    const int t0    = cbase / VV;
    const int coff  = cbase - t0*VV;   // 0..24

    const float* xn = x + (size_t)n*(CC*NCOL);

    // ---- prologue staging ----
    // A_adp fragments: s_Af[((s*4+kt)*4+wt)*2+reg][lane]
    for (int idx = tid; idx < 96*32; idx += 256) {
        int lane_i = idx & 31;
        int r      = idx >> 5;
        int reg = r & 1;
        int wt  = (r >> 1) & 3;
        int kt  = (r >> 3) & 3;
        int s   = r >> 5;
        int gri = lane_i >> 2, tci = lane_i & 3;
        int v = kt*8 + tci + reg*4;
        int w = wt*8 + gri;
        float val = (v < VV && w < VV)
                  ? g_Aadp[((size_t)n*SS + s)*(VV*VV) + v*VV + w] : 0.f;
        s_Af[idx] = __uint_as_float(f2tf32(val));
    }
    if (tid < OCn) s_off[tid] = g_off[tid];

    // warp roles
    const int tl = wid & 3;            // GEMM1 t within tile
    const int oh = wid >> 2;           // GEMM1 m-half / GEMM2 o-half
    const int ctq = wid & 3;           // GEMM2 col quarter

    // x A-fragments in registers (s-invariant; rows = c, cols = v)
    uint32_t ax[2][4][4];
    {
        const int colB = (t0 + tl)*VV;
        #pragma unroll
        for (int mi = 0; mi < 2; mi++) {
            const int r0 = (oh + 2*mi)*16 + gr;
            const float* b0p = xn + (size_t)r0*NCOL;
            const float* b1p = b0p + (size_t)8*NCOL;
            #pragma unroll
            for (int kt = 0; kt < 4; kt++) {
                int c0i = colB + kt*8 + tc;
                int c1i = c0i + 4;
                bool k0 = (c0i < NCOL);
                bool k1 = (c1i < NCOL);
                ax[mi][kt][0] = f2tf32(k0 ? b0p[c0i] : 0.f);
                ax[mi][kt][1] = f2tf32(k0 ? b1p[c0i] : 0.f);
                ax[mi][kt][2] = f2tf32(k1 ? b0p[c1i] : 0.f);
                ax[mi][kt][3] = f2tf32(k1 ? b1p[c1i] : 0.f);
            }
        }
    }
    __syncthreads();   // s_Af ready

    const uint32_t* xmu = reinterpret_cast<const uint32_t*>(s_xm);
    const uint32_t* wu  = reinterpret_cast<const uint32_t*>(s_w);
    const uint32_t* afu = reinterpret_cast<const uint32_t*>(s_Af);
    uint32_t* xmw = reinterpret_cast<uint32_t*>(s_xm);

    float dY[4][4];
    #pragma unroll
    for (int nt = 0; nt < 4; nt++)
        #pragma unroll
        for (int j = 0; j < 4; j++) dY[nt][j] = 0.f;

    for (int s = 0; s < SS; s++) {
        if (s) __syncthreads();   // prior GEMM2 done with s_xm, s_w
        // stage W_s (float4 coalesced; overlaps with GEMM1 below)
        {
            const float4* wg = reinterpret_cast<const float4*>(
                g_wdT + s*(CC*OCn));
            for (int idx = tid; idx < CC*OCn/4; idx += 256) {
                int k = idx >> 4, o4 = (idx & 15) << 2;
                *reinterpret_cast<float4*>(&s_w[k*WST + o4]) = wg[idx];
            }
        }

        // ---- GEMM1 via mma: xm[col][c] from reg-resident x frags ----
        #pragma unroll
        for (int mi = 0; mi < 2; mi++) {
            const int c0 = (oh + 2*mi)*16;
            #pragma unroll
            for (int wt = 0; wt < 4; wt++) {
                float d[4] = {0.f, 0.f, 0.f, 0.f};
                #pragma unroll
                for (int kt = 0; kt < 4; kt++) {
                    int fb = (((s*4 + kt)*4 + wt)*2)*32 + lane;
                    mma_tf32(d, ax[mi][kt][0], ax[mi][kt][1],
                                ax[mi][kt][2], ax[mi][kt][3],
                                afu[fb], afu[fb + 32]);
                }
                int w0  = wt*8 + 2*tc;
                int lc0 = tl*VV + w0 - coff;
                if (w0 < VV && lc0 >= 0 && lc0 < CT) {
                    xmw[lc0*XMS + c0 + gr]     = f2tf32(d[0]);
                    xmw[lc0*XMS + c0 + gr + 8] = f2tf32(d[2]);
                }
                int w1  = w0 + 1;
                int lc1 = lc0 + 1;
                if (w1 < VV && lc1 >= 0 && lc1 < CT) {
                    xmw[lc1*XMS + c0 + gr]     = f2tf32(d[1]);
                    xmw[lc1*XMS + c0 + gr + 8] = f2tf32(d[3]);
                }
            }
        }
        __syncthreads();

        // ---- GEMM2 via mma: K = 64 (this s) ----
        #pragma unroll 2
        for (int kq = 0; kq < 8; kq++) {
            int k = kq*8;
            uint32_t a0 = xmu[(ctq*16 + gr    )*XMS + k + tc];
            uint32_t a1 = xmu[(ctq*16 + gr + 8)*XMS + k + tc];
            uint32_t a2 = xmu[(ctq*16 + gr    )*XMS + k + tc + 4];
            uint32_t a3 = xmu[(ctq*16 + gr + 8)*XMS + k + tc + 4];
            #pragma unroll
            for (int nt = 0; nt < 4; nt++) {
                int o0 = oh*32 + nt*8;
                uint32_t b0 = wu[(k + tc    )*WST + o0 + gr];
                uint32_t b1 = wu[(k + tc + 4)*WST + o0 + gr];
                mma_tf32(dY[nt], a0, a1, a2, a3, b0, b1);
            }
        }
    }

    // ---- epilogue ----
    {
        const int row0 = ctq*16 + gr;
        const int row1 = row0 + 8;
        const int colg0 = cbase + row0;
        const int colg1 = cbase + row1;
        const bool ok0 = (colg0 < NCOL);
        const bool ok1 = (colg1 < NCOL);
        float* on = out + (size_t)n*(CC*NCOL);
        #pragma unroll
        for (int nt = 0; nt < 4; nt++) {
            int oe = oh*32 + nt*8 + 2*tc;
            int oo = oe + 1;
            float offe = s_off[oe], offo = s_off[oo];
            if (ok0) {
                float v0 = dY[nt][0] + offe + xn[(size_t)oe*NCOL + colg0];
                float v1 = dY[nt][1] + offo + xn[(size_t)oo*NCOL + colg0];
                on[(size_t)oe*NCOL + colg0] = fmaxf(v0, 0.f);
                on[(size_t)oo*NCOL + colg0] = fmaxf(v1, 0.f);
            }
            if (ok1) {
                float v2 = dY[nt][2] + offe + xn[(size_t)oe*NCOL + colg1];
                float v3 = dY[nt][3] + offo + xn[(size_t)oo*NCOL + colg1];
                on[(size_t)oe*NCOL + colg1] = fmaxf(v2, 0.f);
                on[(size_t)oo*NCOL + colg1] = fmaxf(v3, 0.f);
            }
        }
    }
}

// ---------------------------------------------------------------------------
extern "C" void kernel_launch(void* const* d_in, const int* in_sizes, int n_in,
                              void* d_out, int out_size)
{
    const float* x     = (const float*)d_in[0];
    const float* A     = (const float*)d_in[1];
    const float* alpha = (const float*)d_in[2];
    const float* caw   = (const float*)d_in[3];
    const float* cab   = (const float*)d_in[4];
    const float* cbw   = (const float*)d_in[5];
    const float* cbb   = (const float*)d_in[6];
    const float* bag   = (const float*)d_in[7];
    const float* babt  = (const float*)d_in[8];
    const float* bam   = (const float*)d_in[9];
    const float* bav   = (const float*)d_in[10];
    const float* bbg   = (const float*)d_in[11];
    const float* bbbt  = (const float*)d_in[12];
    const float* bbm   = (const float*)d_in[13];
    const float* bbv   = (const float*)d_in[14];
    const float* cdw   = (const float*)d_in[15];
    const float* cdb   = (const float*)d_in[16];
    const float* bng   = (const float*)d_in[17];
    const float* bnb   = (const float*)d_in[18];
    const float* bnm   = (const float*)d_in[19];
    const float* bnv   = (const float*)d_in[20];
    float* out = (float*)d_out;

    const int smemB = (CT*XMS + CC*WST + 96*32 + 64) * sizeof(float);
    cudaFuncSetAttribute(kB, cudaFuncAttributeMaxDynamicSharedMemorySize, smemB);

    kW<<<(SS*OCn*CC + 255)/256, 256>>>(cdw, cdb, bng, bnb, bnm, bnv);
    kConv<<<dim3(NTCB, SS, NN), 256>>>(x, caw, cab, cbw, cbb,
                                       bag, babt, bam, bav,
                                       bbg, bbbt, bbm, bbv);
    kM<<<dim3(NCH, SS, NN), 256>>>();
    kA2<<<(NN*SS*VV*VV + 255)/256, 256>>>(A, alpha);
    kB<<<dim3(NTBL, NN), 256, smemB>>>(x, out);
}

// round 12
// speedup vs baseline: 1.7727x; 1.0162x over previous
#include <cuda_runtime.h>
#include <cuda_bf16.h>
#include <cstdint>

#define EPSF 1e-5f

// Problem dims
#define NN  64
#define CC  64
#define TD  300
#define VV  25
#define SS  3
#define ICn 16
#define OCn 64
#define NCOL (TD*VV)          // 7500

// kConv tiling
#define TCB   20
#define NTCB  (TD/TCB)        // 15
#define COLSB (TCB*VV)        // 500

// kM tiling
#define NCH  5
#define KTOT (ICn*TD)         // 4800
#define KCH  (KTOT/NCH)       // 960
#define KST  64
#define NSTG (KCH/KST)        // 15

// kB tiling
#define CT    64                      // cols per block
#define NTBL  ((NCOL + CT - 1)/CT)    // 118
#define XMS   68                      // xm row stride
#define WST   72                      // W row stride

typedef unsigned long long u64;

__device__ __nv_bfloat162 g_ab[(size_t)NN*SS*KTOT*32];
__device__ float g_Mpart[NCH*NN*SS*VV*VV];
__device__ float g_Afrag[(size_t)NN*96*32];  // A_adp in mma frag layout, tf32
__device__ float g_wdT  [SS*CC*OCn];         // [s][c][o], BN-scaled, tf32 bits
__device__ float g_off  [OCn];

__device__ __forceinline__ float tanh_fast(float x) {
    float y;
    asm("tanh.approx.f32 %0, %1;" : "=f"(y) : "f"(x));
    return y;
}
__device__ __forceinline__ u64 pack2(float lo, float hi) {
    u64 r; asm("mov.b64 %0, {%1, %2};" : "=l"(r) : "f"(lo), "f"(hi)); return r;
}
__device__ __forceinline__ float2 unpack2(u64 p) {
    float2 r; asm("mov.b64 {%0, %1}, %2;" : "=f"(r.x), "=f"(r.y) : "l"(p)); return r;
}
__device__ __forceinline__ void fma2(u64& d, u64 a, u64 b) {
    asm("fma.rn.f32x2 %0, %1, %2, %0;" : "+l"(d) : "l"(a), "l"(b));
}
__device__ __forceinline__ uint32_t f2tf32(float x) {
    uint32_t u;
    asm("cvt.rna.tf32.f32 %0, %1;" : "=r"(u) : "f"(x));
    return u;
}
__device__ __forceinline__ void mma_tf32(float d[4],
    uint32_t a0, uint32_t a1, uint32_t a2, uint32_t a3,
    uint32_t b0, uint32_t b1)
{
    asm volatile(
        "mma.sync.aligned.m16n8k8.row.col.f32.tf32.tf32.f32 "
        "{%0,%1,%2,%3}, {%4,%5,%6,%7}, {%8,%9}, {%0,%1,%2,%3};\n"
        : "+f"(d[0]), "+f"(d[1]), "+f"(d[2]), "+f"(d[3])
        : "r"(a0), "r"(a1), "r"(a2), "r"(a3), "r"(b0), "r"(b1));
}

// ---------------------------------------------------------------------------
// kConv (tensor-core): per (chunk, s, n):
//   D[io][col] = sum_c Wab[io][c] * x[c][col]   (io: 0..15 = a, 16..31 = b)
//   out = tanh(D + shift) -> g_ab bf16 pairs. No barriers in main loop.
// chunk0 lets the launch be split (capture-slot control).
// ---------------------------------------------------------------------------
__global__ __launch_bounds__(256, 2) void kConv(
    const float* __restrict__ x,
    const float* __restrict__ wa, const float* __restrict__ ba,
    const float* __restrict__ wb, const float* __restrict__ bb,
    const float* __restrict__ gag, const float* __restrict__ gab,
    const float* __restrict__ gam, const float* __restrict__ gav,
    const float* __restrict__ gbg, const float* __restrict__ gbb,
    const float* __restrict__ gbm, const float* __restrict__ gbv,
    int chunk0)
{
    __shared__ __align__(16) float s_wf[32*68];   // [io][c] tf32 bits
    __shared__ float s_sh[32];                    // shifts: a 0..15, b 16..31

    const int tid  = threadIdx.x;
    const int wid  = tid >> 5;
    const int lane = tid & 31;
    const int gr   = lane >> 2;        // 0..7
    const int tc   = lane & 3;         // 0..3
    const int chunk = blockIdx.x + chunk0;
    const int s     = blockIdx.y;
    const int n     = blockIdx.z;

    // Fold BN into weights (tf32) and shifts
    for (int idx = tid; idx < 32*CC; idx += 256) {
        int io = idx >> 6, c = idx & 63;
        int i  = io & 15;
        bool isB = io >= 16;
        float g  = isB ? gbg[s*ICn+i] : gag[s*ICn+i];
        float vv = isB ? gbv[s*ICn+i] : gav[s*ICn+i];
        float wv = isB ? wb[s*ICn*CC + i*CC + c] : wa[s*ICn*CC + i*CC + c];
        float sc = g * rsqrtf(vv + EPSF);
        s_wf[io*68 + c] = __uint_as_float(f2tf32(wv * sc));
    }
    if (tid < 32) {
        int i = tid & 15;
        bool isB = tid >= 16;
        float g  = isB ? gbg[s*ICn+i] : gag[s*ICn+i];
        float vv = isB ? gbv[s*ICn+i] : gav[s*ICn+i];
        float bs = isB ? bb[s*ICn+i]  : ba[s*ICn+i];
        float mn = isB ? gbm[s*ICn+i] : gam[s*ICn+i];
        float bt = isB ? gbb[s*ICn+i] : gab[s*ICn+i];
        float sc = g * rsqrtf(vv + EPSF);
        s_sh[tid] = (bs - mn) * sc + bt;
    }
    __syncthreads();

    // Hoist all A fragments (weights): 2 m-tiles x 8 k-tiles x 4 regs
    const uint32_t* wfu = reinterpret_cast<const uint32_t*>(s_wf);
    uint32_t af[2][8][4];
    #pragma unroll
    for (int mi = 0; mi < 2; mi++)
        #pragma unroll
        for (int kt = 0; kt < 8; kt++) {
            int r0 = (mi*16 + gr)*68 + kt*8 + tc;
            af[mi][kt][0] = wfu[r0];
            af[mi][kt][1] = wfu[r0 + 8*68];
            af[mi][kt][2] = wfu[r0 + 4];
            af[mi][kt][3] = wfu[r0 + 8*68 + 4];
        }
    const float sha0 = s_sh[gr],      sha8 = s_sh[gr + 8];
    const float shb0 = s_sh[16 + gr], shb8 = s_sh[24 + gr];

    const float* xn = x + (size_t)n*(CC*NCOL);
    __nv_bfloat162* gb = g_ab + (size_t)(n*SS + s)*KTOT*32;

    const int lwbase = wid*64;             // warp's local col base (0..448)

    #pragma unroll 2
    for (int nt = 0; nt < 8; nt++) {
        const int n0 = nt*8;
        const int lcol = lwbase + n0 + gr;               // local col this lane
        const bool ld  = (lcol < COLSB);
        const int colg = chunk*COLSB + lcol;

        // B fragments from gmem (x[c][colg]); zeros in pad region
        uint32_t bf[8][2];
        const float* xp = xn + colg;
        #pragma unroll
        for (int kt = 0; kt < 8; kt++) {
            float v0 = ld ? xp[(size_t)(kt*8 + tc)*NCOL]     : 0.f;
            float v1 = ld ? xp[(size_t)(kt*8 + tc + 4)*NCOL] : 0.f;
            bf[kt][0] = f2tf32(v0);
            bf[kt][1] = f2tf32(v1);
        }

        float da[4] = {0.f, 0.f, 0.f, 0.f};   // a rows (io 0..15)
        float dbv[4] = {0.f, 0.f, 0.f, 0.f};  // b rows (io 16..31)
        #pragma unroll
        for (int kt = 0; kt < 8; kt++) {
            mma_tf32(da,  af[0][kt][0], af[0][kt][1], af[0][kt][2], af[0][kt][3],
                     bf[kt][0], bf[kt][1]);
            mma_tf32(dbv, af[1][kt][0], af[1][kt][1], af[1][kt][2], af[1][kt][3],
                     bf[kt][0], bf[kt][1]);
        }

        // tanh + pack + scatter-store
        float a0 = tanh_fast(da[0] + sha0);
        float a1 = tanh_fast(da[1] + sha0);
        float a2 = tanh_fast(da[2] + sha8);
        float a3 = tanh_fast(da[3] + sha8);
        float b0 = tanh_fast(dbv[0] + shb0);
        float b1 = tanh_fast(dbv[1] + shb0);
        float b2 = tanh_fast(dbv[2] + shb8);
        float b3 = tanh_fast(dbv[3] + shb8);

        const int lc0 = lwbase + n0 + 2*tc;
        if (lc0 < COLSB) {
            int gc = chunk*COLSB + lc0;
            int t = gc / 25, v = gc - 25*t;
            __nv_bfloat162 h0; h0.x = __float2bfloat16(a0); h0.y = __float2bfloat16(b0);
            __nv_bfloat162 h2; h2.x = __float2bfloat16(a2); h2.y = __float2bfloat16(b2);
            gb[(size_t)(t*ICn + gr)*32 + v]     = h0;
            gb[(size_t)(t*ICn + gr + 8)*32 + v] = h2;
        }
        if (lc0 + 1 < COLSB) {
            int gc = chunk*COLSB + lc0 + 1;
            int t = gc / 25, v = gc - 25*t;
            __nv_bfloat162 h1; h1.x = __float2bfloat16(a1); h1.y = __float2bfloat16(b1);
            __nv_bfloat162 h3; h3.x = __float2bfloat16(a3); h3.y = __float2bfloat16(b3);
            gb[(size_t)(t*ICn + gr)*32 + v]     = h1;
            gb[(size_t)(t*ICn + gr + 8)*32 + v] = h3;
        }
    }
}

// ---------------------------------------------------------------------------
// kM: partial M over 960 rows. Register-prefetch double buffering:
// stage st+1's gmem loads issue while stage st computes.
// ---------------------------------------------------------------------------
__global__ __launch_bounds__(256) void kM()
{
    __shared__ __align__(16) float s_a32[KST*32];
    __shared__ __align__(16) float s_b32[KST*32];

    const int tid  = threadIdx.x;
    const int wid  = tid >> 5;
    const int lane = tid & 31;
    const int chunk = blockIdx.x;
    const int s     = blockIdx.y;
    const int n     = blockIdx.z;

    const uint4* gsrc = reinterpret_cast<const uint4*>(
        g_ab + ((size_t)(n*SS + s)*KTOT + (size_t)chunk*KCH)*32);

    u64 macc[2] = {0ull, 0ull};

    // prefetch stage 0
    uint4 pf[2];
    pf[0] = gsrc[tid];
    pf[1] = gsrc[tid + 256];

    for (int st = 0; st < NSTG; st++) {
        __syncthreads();   // prior compute done reading smem
        #pragma unroll
        for (int rep = 0; rep < 2; rep++) {
            int u = tid + rep*256;
            uint4 val = pf[rep];
            int row = u >> 3, q = u & 7;
            float* pa = &s_a32[row*32 + q*4];
            float* pb = &s_b32[row*32 + q*4];
            float2 f0 = __bfloat1622float2(*reinterpret_cast<__nv_bfloat162*>(&val.x));
            float2 f1 = __bfloat1622float2(*reinterpret_cast<__nv_bfloat162*>(&val.y));
            float2 f2 = __bfloat1622float2(*reinterpret_cast<__nv_bfloat162*>(&val.z));
            float2 f3 = __bfloat1622float2(*reinterpret_cast<__nv_bfloat162*>(&val.w));
            pa[0] = f0.x; pb[0] = f0.y;
            pa[1] = f1.x; pb[1] = f1.y;
            pa[2] = f2.x; pb[2] = f2.y;
            pa[3] = f3.x; pb[3] = f3.y;
        }
        // prefetch next stage (independent of smem)
        if (st + 1 < NSTG) {
            pf[0] = gsrc[(st+1)*512 + tid];
            pf[1] = gsrc[(st+1)*512 + tid + 256];
        }
        __syncthreads();
        #pragma unroll 8
        for (int kk = 0; kk < KST; kk++) {
            float av = s_a32[kk*32 + lane];
            u64 ap = pack2(av, av);
            ulonglong2 bv = *reinterpret_cast<const ulonglong2*>(
                &s_b32[kk*32 + wid*4]);
            fma2(macc[0], ap, bv.x);
            fma2(macc[1], ap, bv.y);
        }
    }

    if (lane < VV) {
        float* mp = &g_Mpart[((size_t)chunk*NN*SS + (size_t)n*SS + s)*(VV*VV)];
        float2 m0 = unpack2(macc[0]);
        float2 m1 = unpack2(macc[1]);
        int w = wid*4;
        if (w   < VV) mp[lane*VV + w]   = m0.x;
        if (w+1 < VV) mp[lane*VV + w+1] = m0.y;
        if (w+2 < VV) mp[lane*VV + w+2] = m1.x;
        if (w+3 < VV) mp[lane*VV + w+3] = m1.y;
    }
}

// ---------------------------------------------------------------------------
// kA2: reduce partials, A_adp = A + tanh(M/(IC*T))*alpha, emitted directly in
// kB's mma fragment layout: g_Afrag[n][r][lane] with
//   r = ((s*4+kt)*4+wt)*2+reg,  v = kt*8 + (lane&3) + reg*4,  w = wt*8 + lane>>2
// ---------------------------------------------------------------------------
__global__ void kA2(const float* __restrict__ A, const float* __restrict__ alpha)
{
    int idx = blockIdx.x * 256 + threadIdx.x;
    if (idx >= NN*96*32) return;
    int lane = idx & 31;
    int r    = (idx >> 5) % 96;
    int n    = idx / (96*32);
    int reg = r & 1;
    int wt  = (r >> 1) & 3;
    int kt  = (r >> 3) & 3;
    int s   = r >> 5;
    int v = kt*8 + (lane & 3) + reg*4;
    int w = wt*8 + (lane >> 2);
    float val = 0.f;
    if (v < VV && w < VV) {
        int mi = (n*SS + s)*(VV*VV) + v*VV + w;
        float m = 0.f;
        #pragma unroll
        for (int ch = 0; ch < NCH; ch++)
            m += g_Mpart[ch*(NN*SS*VV*VV) + mi];
        val = A[s*(VV*VV) + v*VV + w]
            + tanhf(m * (1.f/(float)(ICn*TD))) * alpha[0];
    }
    g_Afrag[idx] = __uint_as_float(f2tf32(val));
}

// ---------------------------------------------------------------------------
// kW: W -> [s][c][o], BN scale folded, tf32-rounded. g_off.
// ---------------------------------------------------------------------------
__global__ void kW(const float* __restrict__ wd, const float* __restrict__ db,
                   const float* __restrict__ bng, const float* __restrict__ bnb,
                   const float* __restrict__ bnm, const float* __restrict__ bnv)
{
    int idx = blockIdx.x * 256 + threadIdx.x;
    if (idx < SS*OCn*CC) {
        int c = idx & 63;
        int o = (idx >> 6) & 63;
        int s = idx >> 12;
        float sc = bng[o] * rsqrtf(bnv[o] + EPSF);
        uint32_t t = f2tf32(wd[idx] * sc);
        g_wdT[s*(CC*OCn) + c*OCn + o] = __uint_as_float(t);
    }
    if (blockIdx.x == 0 && threadIdx.x < OCn) {
        int o = threadIdx.x;
        float sc = bng[o] * rsqrtf(bnv[o] + EPSF);
        float ds = db[o] + db[OCn + o] + db[2*OCn + o];
        g_off[o] = (ds - bnm[o]) * sc + bnb[o];
    }
}

// ---------------------------------------------------------------------------
// kB: block = (64-col tile, n), 4 blocks/SM. x A-fragments in registers;
// A_adp frags copied linearly from g_Afrag. For each s:
//   GEMM1 (mma tf32): xm[col][c] = sum_v x[c][t,v] * Aad_s[v][w(col)]
//   GEMM2 (mma tf32): D[col][o] += xm[col][c] * W_s[c][o]
// Epilogue: D + off + residual, ReLU.
// ---------------------------------------------------------------------------
__global__ __launch_bounds__(256, 4) void kB(
    const float* __restrict__ x,
    float* __restrict__ out)
{
    extern __shared__ float sm[];
    float* s_xm  = sm;                  // [64][68]  tf32 bits
    float* s_w   = s_xm + CT*XMS;       // [64][72]  tf32 bits (per s)
    float* s_Af  = s_w  + CC*WST;       // [96][32]  A_adp frags, tf32
    float* s_off = s_Af + 96*32;        // [64]

    const int tid  = threadIdx.x;
    const int wid  = tid >> 5;
    const int lane = tid & 31;
    const int gr   = lane >> 2;        // 0..7
    const int tc   = lane & 3;         // 0..3
    const int blk  = blockIdx.x;
    const int n    = blockIdx.y;
    const int cbase = blk * CT;
    const int t0    = cbase / VV;
    const int coff  = cbase - t0*VV;   // 0..24

    const float* xn = x + (size_t)n*(CC*NCOL);

    // ---- prologue staging ----
    // A_adp fragments: linear copy (g_Afrag is L2-resident, reused 118x)
    {
        const float4* ag = reinterpret_cast<const float4*>(
            g_Afrag + (size_t)n*(96*32));
        float4* as = reinterpret_cast<float4*>(s_Af);
        for (int idx = tid; idx < 96*32/4; idx += 256)
            as[idx] = ag[idx];
    }
    if (tid < OCn) s_off[tid] = g_off[tid];

    // warp roles
    const int tl = wid & 3;            // GEMM1 t within tile
    const int oh = wid >> 2;           // GEMM1 m-half / GEMM2 o-half
    const int ctq = wid & 3;           // GEMM2 col quarter

    // x A-fragments in registers (s-invariant; rows = c, cols = v)
    uint32_t ax[2][4][4];
    {
        const int colB = (t0 + tl)*VV;
        #pragma unroll
        for (int mi = 0; mi < 2; mi++) {
            const int r0 = (oh + 2*mi)*16 + gr;
            const float* b0p = xn + (size_t)r0*NCOL;
            const float* b1p = b0p + (size_t)8*NCOL;
            #pragma unroll
            for (int kt = 0; kt < 4; kt++) {
                int c0i = colB + kt*8 + tc;
                int c1i = c0i + 4;
                bool k0 = (c0i < NCOL);
                bool k1 = (c1i < NCOL);
                ax[mi][kt][0] = f2tf32(k0 ? b0p[c0i] : 0.f);
                ax[mi][kt][1] = f2tf32(k0 ? b1p[c0i] : 0.f);
                ax[mi][kt][2] = f2tf32(k1 ? b0p[c1i] : 0.f);
                ax[mi][kt][3] = f2tf32(k1 ? b1p[c1i] : 0.f);
            }
        }
    }
    __syncthreads();   // s_Af ready

    const uint32_t* xmu = reinterpret_cast<const uint32_t*>(s_xm);
    const uint32_t* wu  = reinterpret_cast<const uint32_t*>(s_w);
    const uint32_t* afu = reinterpret_cast<const uint32_t*>(s_Af);
    uint32_t* xmw = reinterpret_cast<uint32_t*>(s_xm);

    float dY[4][4];
    #pragma unroll
    for (int nt = 0; nt < 4; nt++)
        #pragma unroll
        for (int j = 0; j < 4; j++) dY[nt][j] = 0.f;

    for (int s = 0; s < SS; s++) {
        if (s) __syncthreads();   // prior GEMM2 done with s_xm, s_w
        // stage W_s (float4 coalesced; overlaps with GEMM1 below)
        {
            const float4* wg = reinterpret_cast<const float4*>(
                g_wdT + s*(CC*OCn));
            for (int idx = tid; idx < CC*OCn/4; idx += 256) {
                int k = idx >> 4, o4 = (idx & 15) << 2;
                *reinterpret_cast<float4*>(&s_w[k*WST + o4]) = wg[idx];
            }
        }

        // ---- GEMM1 via mma: xm[col][c] from reg-resident x frags ----
        #pragma unroll
        for (int mi = 0; mi < 2; mi++) {
            const int c0 = (oh + 2*mi)*16;
            #pragma unroll
            for (int wt = 0; wt < 4; wt++) {
                float d[4] = {0.f, 0.f, 0.f, 0.f};
                #pragma unroll
                for (int kt = 0; kt < 4; kt++) {
                    int fb = (((s*4 + kt)*4 + wt)*2)*32 + lane;
                    mma_tf32(d, ax[mi][kt][0], ax[mi][kt][1],
                                ax[mi][kt][2], ax[mi][kt][3],
                                afu[fb], afu[fb + 32]);
                }
                int w0  = wt*8 + 2*tc;
                int lc0 = tl*VV + w0 - coff;
                if (w0 < VV && lc0 >= 0 && lc0 < CT) {
                    xmw[lc0*XMS + c0 + gr]     = f2tf32(d[0]);
                    xmw[lc0*XMS + c0 + gr + 8] = f2tf32(d[2]);
                }
                int w1  = w0 + 1;
                int lc1 = lc0 + 1;
                if (w1 < VV && lc1 >= 0 && lc1 < CT) {
                    xmw[lc1*XMS + c0 + gr]     = f2tf32(d[1]);
                    xmw[lc1*XMS + c0 + gr + 8] = f2tf32(d[3]);
                }
            }
        }
        __syncthreads();

        // ---- GEMM2 via mma: K = 64 (this s) ----
        #pragma unroll 2
        for (int kq = 0; kq < 8; kq++) {
            int k = kq*8;
            uint32_t a0 = xmu[(ctq*16 + gr    )*XMS + k + tc];
            uint32_t a1 = xmu[(ctq*16 + gr + 8)*XMS + k + tc];
            uint32_t a2 = xmu[(ctq*16 + gr    )*XMS + k + tc + 4];
            uint32_t a3 = xmu[(ctq*16 + gr + 8)*XMS + k + tc + 4];
            #pragma unroll
            for (int nt = 0; nt < 4; nt++) {
                int o0 = oh*32 + nt*8;
                uint32_t b0 = wu[(k + tc    )*WST + o0 + gr];
                uint32_t b1 = wu[(k + tc + 4)*WST + o0 + gr];
                mma_tf32(dY[nt], a0, a1, a2, a3, b0, b1);
            }
        }
    }

    // ---- epilogue ----
    {
        const int row0 = ctq*16 + gr;
        const int row1 = row0 + 8;
        const int colg0 = cbase + row0;
        const int colg1 = cbase + row1;
        const bool ok0 = (colg0 < NCOL);
        const bool ok1 = (colg1 < NCOL);
        float* on = out + (size_t)n*(CC*NCOL);
        #pragma unroll
        for (int nt = 0; nt < 4; nt++) {
            int oe = oh*32 + nt*8 + 2*tc;
            int oo = oe + 1;
            float offe = s_off[oe], offo = s_off[oo];
            if (ok0) {
                float v0 = dY[nt][0] + offe + xn[(size_t)oe*NCOL + colg0];
                float v1 = dY[nt][1] + offo + xn[(size_t)oo*NCOL + colg0];
                on[(size_t)oe*NCOL + colg0] = fmaxf(v0, 0.f);
                on[(size_t)oo*NCOL + colg0] = fmaxf(v1, 0.f);
            }
            if (ok1) {
                float v2 = dY[nt][2] + offe + xn[(size_t)oe*NCOL + colg1];
                float v3 = dY[nt][3] + offo + xn[(size_t)oo*NCOL + colg1];
                on[(size_t)oe*NCOL + colg1] = fmaxf(v2, 0.f);
                on[(size_t)oo*NCOL + colg1] = fmaxf(v3, 0.f);
            }
        }
    }
}

// ---------------------------------------------------------------------------
extern "C" void kernel_launch(void* const* d_in, const int* in_sizes, int n_in,
                              void* d_out, int out_size)
{
    const float* x     = (const float*)d_in[0];
    const float* A     = (const float*)d_in[1];
    const float* alpha = (const float*)d_in[2];
    const float* caw   = (const float*)d_in[3];
    const float* cab   = (const float*)d_in[4];
    const float* cbw   = (const float*)d_in[5];
    const float* cbb   = (const float*)d_in[6];
    const float* bag   = (const float*)d_in[7];
    const float* babt  = (const float*)d_in[8];
    const float* bam   = (const float*)d_in[9];
    const float* bav   = (const float*)d_in[10];
    const float* bbg   = (const float*)d_in[11];
    const float* bbbt  = (const float*)d_in[12];
    const float* bbm   = (const float*)d_in[13];
    const float* bbv   = (const float*)d_in[14];
    const float* cdw   = (const float*)d_in[15];
    const float* cdb   = (const float*)d_in[16];
    const float* bng   = (const float*)d_in[17];
    const float* bnb   = (const float*)d_in[18];
    const float* bnm   = (const float*)d_in[19];
    const float* bnv   = (const float*)d_in[20];
    float* out = (float*)d_out;

    const int smemB = (CT*XMS + CC*WST + 96*32 + 64) * sizeof(float);
    cudaFuncSetAttribute(kB, cudaFuncAttributeMaxDynamicSharedMemorySize, smemB);

    // launch order chosen so kM is the 4th launch (ncu capture slot)
    kW<<<(SS*OCn*CC + 255)/256, 256>>>(cdw, cdb, bng, bnb, bnm, bnv);
    kConv<<<dim3(8, SS, NN), 256>>>(x, caw, cab, cbw, cbb,
                                    bag, babt, bam, bav,
                                    bbg, bbbt, bbm, bbv, 0);
    kConv<<<dim3(NTCB - 8, SS, NN), 256>>>(x, caw, cab, cbw, cbb,
                                           bag, babt, bam, bav,
                                           bbg, bbbt, bbm, bbv, 8);
    kM<<<dim3(NCH, SS, NN), 256>>>();
    kA2<<<(NN*96*32 + 255)/256, 256>>>(A, alpha);
    kB<<<dim3(NTBL, NN), 256, smemB>>>(x, out);
}

// round 13
// speedup vs baseline: 2.0222x; 1.1407x over previous
#include <cuda_runtime.h>
#include <cuda_bf16.h>
#include <cstdint>

#define EPSF 1e-5f

// Problem dims
#define NN  64
#define CC  64
#define TD  300
#define VV  25
#define SS  3
#define ICn 16
#define OCn 64
#define NCOL (TD*VV)          // 7500

// kConv tiling
#define TCB   20
#define NTCB  (TD/TCB)        // 15
#define COLSB (TCB*VV)        // 500

// kM tiling
#define NCH  5
#define STEPS_PER_CH (TD/NCH) // 60 k16-steps per chunk (step == t)

// kB tiling
#define CT    64                      // cols per block
#define NTBL  ((NCOL + CT - 1)/CT)    // 118
#define XMS   68                      // xm row stride
#define WST   72                      // W row stride

typedef unsigned long long u64;

// a/b in bf16 mma-fragment layout, one 1KB step-block per (n,s,t):
//   g_aF: [ns][t][mt 2][reg 4][lane 32] u32 (bf16x2 k-pairs)
//   g_bF: [ns][t][wt 4][reg 2][lane 32] u32
__device__ uint32_t g_aF[(size_t)NN*SS*TD*256];
__device__ uint32_t g_bF[(size_t)NN*SS*TD*256];
__device__ float g_Mpart[NCH*NN*SS*VV*VV];
__device__ float g_Afrag[(size_t)NN*96*32];  // A_adp in mma frag layout, tf32
__device__ float g_wdT  [SS*CC*OCn];         // [s][c][o], BN-scaled, tf32 bits
__device__ float g_off  [OCn];

__device__ __forceinline__ float tanh_fast(float x) {
    float y;
    asm("tanh.approx.f32 %0, %1;" : "=f"(y) : "f"(x));
    return y;
}
__device__ __forceinline__ uint32_t f2tf32(float x) {
    uint32_t u;
    asm("cvt.rna.tf32.f32 %0, %1;" : "=r"(u) : "f"(x));
    return u;
}
__device__ __forceinline__ uint32_t prmt(uint32_t a, uint32_t b, uint32_t sel) {
    uint32_t d;
    asm("prmt.b32 %0, %1, %2, %3;" : "=r"(d) : "r"(a), "r"(b), "r"(sel));
    return d;
}
__device__ __forceinline__ uint32_t bfpack(float lo, float hi) {
    __nv_bfloat162 h = __floats2bfloat162_rn(lo, hi);   // .x = lo (low 16 bits)
    return *reinterpret_cast<uint32_t*>(&h);
}
__device__ __forceinline__ void mma_tf32(float d[4],
    uint32_t a0, uint32_t a1, uint32_t a2, uint32_t a3,
    uint32_t b0, uint32_t b1)
{
    asm volatile(
        "mma.sync.aligned.m16n8k8.row.col.f32.tf32.tf32.f32 "
        "{%0,%1,%2,%3}, {%4,%5,%6,%7}, {%8,%9}, {%0,%1,%2,%3};\n"
        : "+f"(d[0]), "+f"(d[1]), "+f"(d[2]), "+f"(d[3])
        : "r"(a0), "r"(a1), "r"(a2), "r"(a3), "r"(b0), "r"(b1));
}
__device__ __forceinline__ void mma_bf16(float d[4],
    uint32_t a0, uint32_t a1, uint32_t a2, uint32_t a3,
    uint32_t b0, uint32_t b1)
{
    asm volatile(
        "mma.sync.aligned.m16n8k16.row.col.f32.bf16.bf16.f32 "
        "{%0,%1,%2,%3}, {%4,%5,%6,%7}, {%8,%9}, {%0,%1,%2,%3};\n"
        : "+f"(d[0]), "+f"(d[1]), "+f"(d[2]), "+f"(d[3])
        : "r"(a0), "r"(a1), "r"(a2), "r"(a3), "r"(b0), "r"(b1));
}

// ---------------------------------------------------------------------------
// kConv (tensor-core): per (chunk, s, n):
//   D[io][col] = sum_c Wab[io][c] * x[c][col]   (io: 0..15 = a, 16..31 = b)
//   out = tanh(D + shift) -> g_aF/g_bF bf16 mma fragments.
// k-pair assembly: shfl_xor(4) pairs i=gr with i=gr+1; even-gr lanes emit
// a-frag words, odd-gr lanes emit b-frag words.
// ---------------------------------------------------------------------------
__global__ __launch_bounds__(256, 2) void kConv(
    const float* __restrict__ x,
    const float* __restrict__ wa, const float* __restrict__ ba,
    const float* __restrict__ wb, const float* __restrict__ bb,
    const float* __restrict__ gag, const float* __restrict__ gab,
    const float* __restrict__ gam, const float* __restrict__ gav,
    const float* __restrict__ gbg, const float* __restrict__ gbb,
    const float* __restrict__ gbm, const float* __restrict__ gbv,
    int chunk0)
{
    __shared__ __align__(16) float s_wf[32*68];   // [io][c] tf32 bits
    __shared__ float s_sh[32];                    // shifts: a 0..15, b 16..31

    const int tid  = threadIdx.x;
    const int wid  = tid >> 5;
    const int lane = tid & 31;
    const int gr   = lane >> 2;        // 0..7
    const int tc   = lane & 3;         // 0..3
    const int chunk = blockIdx.x + chunk0;
    const int s     = blockIdx.y;
    const int n     = blockIdx.z;

    // Fold BN into weights (tf32) and shifts
    for (int idx = tid; idx < 32*CC; idx += 256) {
        int io = idx >> 6, c = idx & 63;
        int i  = io & 15;
        bool isB = io >= 16;
        float g  = isB ? gbg[s*ICn+i] : gag[s*ICn+i];
        float vv = isB ? gbv[s*ICn+i] : gav[s*ICn+i];
        float wv = isB ? wb[s*ICn*CC + i*CC + c] : wa[s*ICn*CC + i*CC + c];
        float sc = g * rsqrtf(vv + EPSF);
        s_wf[io*68 + c] = __uint_as_float(f2tf32(wv * sc));
    }
    if (tid < 32) {
        int i = tid & 15;
        bool isB = tid >= 16;
        float g  = isB ? gbg[s*ICn+i] : gag[s*ICn+i];
        float vv = isB ? gbv[s*ICn+i] : gav[s*ICn+i];
        float bs = isB ? bb[s*ICn+i]  : ba[s*ICn+i];
        float mn = isB ? gbm[s*ICn+i] : gam[s*ICn+i];
        float bt = isB ? gbb[s*ICn+i] : gab[s*ICn+i];
        float sc = g * rsqrtf(vv + EPSF);
        s_sh[tid] = (bs - mn) * sc + bt;
    }
    __syncthreads();

    // Hoist all A fragments (weights): 2 m-tiles x 8 k-tiles x 4 regs
    const uint32_t* wfu = reinterpret_cast<const uint32_t*>(s_wf);
    uint32_t af[2][8][4];
    #pragma unroll
    for (int mi = 0; mi < 2; mi++)
        #pragma unroll
        for (int kt = 0; kt < 8; kt++) {
            int r0 = (mi*16 + gr)*68 + kt*8 + tc;
            af[mi][kt][0] = wfu[r0];
            af[mi][kt][1] = wfu[r0 + 8*68];
            af[mi][kt][2] = wfu[r0 + 4];
            af[mi][kt][3] = wfu[r0 + 8*68 + 4];
        }
    const float sha0 = s_sh[gr],      sha8 = s_sh[gr + 8];
    const float shb0 = s_sh[16 + gr], shb8 = s_sh[24 + gr];

    const float* xn = x + (size_t)n*(CC*NCOL);
    const size_t nsbase = (size_t)(n*SS + s)*TD*256;

    const int lwbase = wid*64;             // warp's local col base (0..448)
    const int tck = gr >> 1;               // k-pair index this lane produces
    const bool evenGr = ((gr & 1) == 0);

    #pragma unroll 2
    for (int nt = 0; nt < 8; nt++) {
        const int n0 = nt*8;
        const int lcol = lwbase + n0 + gr;               // B-frag col this lane
        const bool ld  = (lcol < COLSB);
        const int colg = chunk*COLSB + lcol;

        // B fragments from gmem (x[c][colg]); zeros in pad region
        uint32_t bf[8][2];
        const float* xp = xn + colg;
        #pragma unroll
        for (int kt = 0; kt < 8; kt++) {
            float v0 = ld ? xp[(size_t)(kt*8 + tc)*NCOL]     : 0.f;
            float v1 = ld ? xp[(size_t)(kt*8 + tc + 4)*NCOL] : 0.f;
            bf[kt][0] = f2tf32(v0);
            bf[kt][1] = f2tf32(v1);
        }

        float da[4] = {0.f, 0.f, 0.f, 0.f};   // a rows (io 0..15)
        float dbv[4] = {0.f, 0.f, 0.f, 0.f};  // b rows (io 16..31)
        #pragma unroll
        for (int kt = 0; kt < 8; kt++) {
            mma_tf32(da,  af[0][kt][0], af[0][kt][1], af[0][kt][2], af[0][kt][3],
                     bf[kt][0], bf[kt][1]);
            mma_tf32(dbv, af[1][kt][0], af[1][kt][1], af[1][kt][2], af[1][kt][3],
                     bf[kt][0], bf[kt][1]);
        }

        // tanh + bf16x2 pack (per i-row, cols (lc0, lc0+1))
        uint32_t ha  = bfpack(tanh_fast(da[0]  + sha0), tanh_fast(da[1]  + sha0));
        uint32_t ha8 = bfpack(tanh_fast(da[2]  + sha8), tanh_fast(da[3]  + sha8));
        uint32_t hb  = bfpack(tanh_fast(dbv[0] + shb0), tanh_fast(dbv[1] + shb0));
        uint32_t hb8 = bfpack(tanh_fast(dbv[2] + shb8), tanh_fast(dbv[3] + shb8));

        // exchange with gr^1 partner (lane ^ 4)
        uint32_t pa  = __shfl_xor_sync(0xffffffffu, ha,  4);
        uint32_t pa8 = __shfl_xor_sync(0xffffffffu, ha8, 4);
        uint32_t pb  = __shfl_xor_sync(0xffffffffu, hb,  4);
        uint32_t pb8 = __shfl_xor_sync(0xffffffffu, hb8, 4);

        const int lc0 = lwbase + n0 + 2*tc;

        if (evenGr) {
            // a-frag words: k-pair (gr, gr+1) lo, (gr+8, gr+9) hi
            uint32_t wlo0 = prmt(ha,  pa,  0x5410);  // col lc0
            uint32_t whi0 = prmt(ha8, pa8, 0x5410);
            uint32_t wlo1 = prmt(ha,  pa,  0x7632);  // col lc0+1
            uint32_t whi1 = prmt(ha8, pa8, 0x7632);
            #pragma unroll
            for (int cc2 = 0; cc2 < 2; cc2++) {
                int lc = lc0 + cc2;
                if (lc < COLSB) {
                    int gc = chunk*COLSB + lc;
                    int t = gc / 25, v = gc - 25*t;
                    int mt = v >> 4, vt = v & 15;
                    int rsel = vt >> 3, grt = vt & 7;
                    size_t sb = nsbase + (size_t)t*256;
                    uint32_t wlo = cc2 ? wlo1 : wlo0;
                    uint32_t whi = cc2 ? whi1 : whi0;
                    g_aF[sb + (mt*4 + rsel    )*32 + grt*4 + tck] = wlo;
                    g_aF[sb + (mt*4 + 2 + rsel)*32 + grt*4 + tck] = whi;
                }
            }
        } else {
            // b-frag words: k-pair (gr-1, gr) lo, (gr+7, gr+8) hi
            uint32_t wlo0 = prmt(pb,  hb,  0x5410);
            uint32_t whi0 = prmt(pb8, hb8, 0x5410);
            uint32_t wlo1 = prmt(pb,  hb,  0x7632);
            uint32_t whi1 = prmt(pb8, hb8, 0x7632);
            #pragma unroll
            for (int cc2 = 0; cc2 < 2; cc2++) {
                int lc = lc0 + cc2;
                if (lc < COLSB) {
                    int gc = chunk*COLSB + lc;
                    int t = gc / 25, v = gc - 25*t;
                    int wt = v >> 3, grw = v & 7;
                    size_t sb = nsbase + (size_t)t*256;
                    uint32_t wlo = cc2 ? wlo1 : wlo0;
                    uint32_t whi = cc2 ? whi1 : whi0;
                    g_bF[sb + (wt*2    )*32 + grw*4 + tck] = wlo;
                    g_bF[sb + (wt*2 + 1)*32 + grw*4 + tck] = whi;
                }
            }
        }
    }
}

// ---------------------------------------------------------------------------
// kM (tensor-core): partial M[v,w] over this chunk's 60 k16-steps.
// Pure LDG(frag) + bf16 mma; 8-warp split-k, smem tree reduction.
// ---------------------------------------------------------------------------
__global__ __launch_bounds__(256) void kM()
{
    __shared__ float s_red[8*1024];

    const int tid  = threadIdx.x;
    const int wid  = tid >> 5;
    const int lane = tid & 31;
    const int chunk = blockIdx.x;
    const int s     = blockIdx.y;
    const int n     = blockIdx.z;

    const size_t base = ((size_t)(n*SS + s)*TD + chunk*STEPS_PER_CH)*256;
    const uint32_t* ga = g_aF + base + lane;
    const uint32_t* gb = g_bF + base + lane;

    float acc[2][4][4];
    #pragma unroll
    for (int mt = 0; mt < 2; mt++)
        #pragma unroll
        for (int wt = 0; wt < 4; wt++)
            #pragma unroll
            for (int r = 0; r < 4; r++) acc[mt][wt][r] = 0.f;

    for (int ls = wid; ls < STEPS_PER_CH; ls += 8) {
        const uint32_t* pa = ga + ls*256;
        const uint32_t* pb = gb + ls*256;
        uint32_t aw[2][4], bw[4][2];
        #pragma unroll
        for (int mt = 0; mt < 2; mt++)
            #pragma unroll
            for (int r = 0; r < 4; r++)
                aw[mt][r] = pa[(mt*4 + r)*32];
        #pragma unroll
        for (int wt = 0; wt < 4; wt++)
            #pragma unroll
            for (int r = 0; r < 2; r++)
                bw[wt][r] = pb[(wt*2 + r)*32];
        #pragma unroll
        for (int mt = 0; mt < 2; mt++)
            #pragma unroll
            for (int wt = 0; wt < 4; wt++)
                mma_bf16(acc[mt][wt], aw[mt][0], aw[mt][1], aw[mt][2], aw[mt][3],
                         bw[wt][0], bw[wt][1]);
    }

    float* my = s_red + wid*1024;
    #pragma unroll
    for (int mt = 0; mt < 2; mt++)
        #pragma unroll
        for (int wt = 0; wt < 4; wt++)
            #pragma unroll
            for (int r = 0; r < 4; r++)
                my[((mt*4 + wt)*4 + r)*32 + lane] = acc[mt][wt][r];
    __syncthreads();

    #pragma unroll
    for (int rep = 0; rep < 4; rep++) {
        int pos = tid + rep*256;
        float v = 0.f;
        #pragma unroll
        for (int w8 = 0; w8 < 8; w8++)
            v += s_red[w8*1024 + pos];
        int lp  = pos & 31;
        int reg = (pos >> 5) & 3;
        int wt  = (pos >> 7) & 3;
        int mt  = pos >> 9;
        int grp = lp >> 2, tcp = lp & 3;
        int vv = mt*16 + grp + (reg >> 1)*8;
        int ww = wt*8 + 2*tcp + (reg & 1);
        if (vv < VV && ww < VV)
            g_Mpart[((size_t)chunk*NN*SS + (size_t)n*SS + s)*(VV*VV)
                    + vv*VV + ww] = v;
    }
}

// ---------------------------------------------------------------------------
// kA2: reduce partials, A_adp = A + tanh(M/(IC*T))*alpha, emitted directly in
// kB's mma fragment layout.
// ---------------------------------------------------------------------------
__global__ void kA2(const float* __restrict__ A, const float* __restrict__ alpha)
{
    int idx = blockIdx.x * 256 + threadIdx.x;
    if (idx >= NN*96*32) return;
    int lane = idx & 31;
    int r    = (idx >> 5) % 96;
    int n    = idx / (96*32);
    int reg = r & 1;
    int wt  = (r >> 1) & 3;
    int kt  = (r >> 3) & 3;
    int s   = r >> 5;
    int v = kt*8 + (lane & 3) + reg*4;
    int w = wt*8 + (lane >> 2);
    float val = 0.f;
    if (v < VV && w < VV) {
        int mi = (n*SS + s)*(VV*VV) + v*VV + w;
        float m = 0.f;
        #pragma unroll
        for (int ch = 0; ch < NCH; ch++)
            m += g_Mpart[ch*(NN*SS*VV*VV) + mi];
        val = A[s*(VV*VV) + v*VV + w]
            + tanhf(m * (1.f/(float)(ICn*TD))) * alpha[0];
    }
    g_Afrag[idx] = __uint_as_float(f2tf32(val));
}

// ---------------------------------------------------------------------------
// kW: W -> [s][c][o], BN scale folded, tf32-rounded. g_off.
// ---------------------------------------------------------------------------
__global__ void kW(const float* __restrict__ wd, const float* __restrict__ db,
                   const float* __restrict__ bng, const float* __restrict__ bnb,
                   const float* __restrict__ bnm, const float* __restrict__ bnv)
{
    int idx = blockIdx.x * 256 + threadIdx.x;
    if (idx < SS*OCn*CC) {
        int c = idx & 63;
        int o = (idx >> 6) & 63;
        int s = idx >> 12;
        float sc = bng[o] * rsqrtf(bnv[o] + EPSF);
        uint32_t t = f2tf32(wd[idx] * sc);
        g_wdT[s*(CC*OCn) + c*OCn + o] = __uint_as_float(t);
    }
    if (blockIdx.x == 0 && threadIdx.x < OCn) {
        int o = threadIdx.x;
        float sc = bng[o] * rsqrtf(bnv[o] + EPSF);
        float ds = db[o] + db[OCn + o] + db[2*OCn + o];
        g_off[o] = (ds - bnm[o]) * sc + bnb[o];
    }
}

// ---------------------------------------------------------------------------
// kB: block = (64-col tile, n), 4 blocks/SM. x A-fragments in registers;
// A_adp frags copied linearly from g_Afrag. For each s:
//   GEMM1 (mma tf32): xm[col][c] = sum_v x[c][t,v] * Aad_s[v][w(col)]
//   GEMM2 (mma tf32): D[col][o] += xm[col][c] * W_s[c][o]
// Epilogue: D + off + residual, ReLU.
// ---------------------------------------------------------------------------
__global__ __launch_bounds__(256, 4) void kB(
    const float* __restrict__ x,
    float* __restrict__ out)
{
    extern __shared__ float sm[];
    float* s_xm  = sm;                  // [64][68]  tf32 bits
    float* s_w   = s_xm + CT*XMS;       // [64][72]  tf32 bits (per s)
    float* s_Af  = s_w  + CC*WST;       // [96][32]  A_adp frags, tf32
    float* s_off = s_Af + 96*32;        // [64]

    const int tid  = threadIdx.x;
    const int wid  = tid >> 5;
    const int lane = tid & 31;
    const int gr   = lane >> 2;        // 0..7
    const int tc   = lane & 3;         // 0..3
    const int blk  = blockIdx.x;
    const int n    = blockIdx.y;
    const int cbase = blk * CT;
    const int t0    = cbase / VV;
    const int coff  = cbase - t0*VV;   // 0..24

    const float* xn = x + (size_t)n*(CC*NCOL);

    // ---- prologue staging ----
    {
        const float4* ag = reinterpret_cast<const float4*>(
            g_Afrag + (size_t)n*(96*32));
        float4* as = reinterpret_cast<float4*>(s_Af);
        for (int idx = tid; idx < 96*32/4; idx += 256)
            as[idx] = ag[idx];
    }
    if (tid < OCn) s_off[tid] = g_off[tid];

    // warp roles
    const int tl = wid & 3;            // GEMM1 t within tile
    const int oh = wid >> 2;           // GEMM1 m-half / GEMM2 o-half
    const int ctq = wid & 3;           // GEMM2 col quarter

    // x A-fragments in registers (s-invariant; rows = c, cols = v)
    uint32_t ax[2][4][4];
    {
        const int colB = (t0 + tl)*VV;
        #pragma unroll
        for (int mi = 0; mi < 2; mi++) {
            const int r0 = (oh + 2*mi)*16 + gr;
            const float* b0p = xn + (size_t)r0*NCOL;
            const float* b1p = b0p + (size_t)8*NCOL;
            #pragma unroll
            for (int kt = 0; kt < 4; kt++) {
                int c0i = colB + kt*8 + tc;
                int c1i = c0i + 4;
                bool k0 = (c0i < NCOL);
                bool k1 = (c1i < NCOL);
                ax[mi][kt][0] = f2tf32(k0 ? b0p[c0i] : 0.f);
                ax[mi][kt][1] = f2tf32(k0 ? b1p[c0i] : 0.f);
                ax[mi][kt][2] = f2tf32(k1 ? b0p[c1i] : 0.f);
                ax[mi][kt][3] = f2tf32(k1 ? b1p[c1i] : 0.f);
            }
        }
    }
    __syncthreads();   // s_Af ready

    const uint32_t* xmu = reinterpret_cast<const uint32_t*>(s_xm);
    const uint32_t* wu  = reinterpret_cast<const uint32_t*>(s_w);
    const uint32_t* afu = reinterpret_cast<const uint32_t*>(s_Af);
    uint32_t* xmw = reinterpret_cast<uint32_t*>(s_xm);

    float dY[4][4];
    #pragma unroll
    for (int nt = 0; nt < 4; nt++)
        #pragma unroll
        for (int j = 0; j < 4; j++) dY[nt][j] = 0.f;

    for (int s = 0; s < SS; s++) {
        if (s) __syncthreads();   // prior GEMM2 done with s_xm, s_w
        // stage W_s (float4 coalesced; overlaps with GEMM1 below)
        {
            const float4* wg = reinterpret_cast<const float4*>(
                g_wdT + s*(CC*OCn));
            for (int idx = tid; idx < CC*OCn/4; idx += 256) {
                int k = idx >> 4, o4 = (idx & 15) << 2;
                *reinterpret_cast<float4*>(&s_w[k*WST + o4]) = wg[idx];
            }
        }

        // ---- GEMM1 via mma: xm[col][c] from reg-resident x frags ----
        #pragma unroll
        for (int mi = 0; mi < 2; mi++) {
            const int c0 = (oh + 2*mi)*16;
            #pragma unroll
            for (int wt = 0; wt < 4; wt++) {
                float d[4] = {0.f, 0.f, 0.f, 0.f};
                #pragma unroll
                for (int kt = 0; kt < 4; kt++) {
                    int fb = (((s*4 + kt)*4 + wt)*2)*32 + lane;
                    mma_tf32(d, ax[mi][kt][0], ax[mi][kt][1],
                                ax[mi][kt][2], ax[mi][kt][3],
                                afu[fb], afu[fb + 32]);
                }
                int w0  = wt*8 + 2*tc;
                int lc0 = tl*VV + w0 - coff;
                if (w0 < VV && lc0 >= 0 && lc0 < CT) {
                    xmw[lc0*XMS + c0 + gr]     = f2tf32(d[0]);
                    xmw[lc0*XMS + c0 + gr + 8] = f2tf32(d[2]);
                }
                int w1  = w0 + 1;
                int lc1 = lc0 + 1;
                if (w1 < VV && lc1 >= 0 && lc1 < CT) {
                    xmw[lc1*XMS + c0 + gr]     = f2tf32(d[1]);
                    xmw[lc1*XMS + c0 + gr + 8] = f2tf32(d[3]);
                }
            }
        }
        __syncthreads();

        // ---- GEMM2 via mma: K = 64 (this s) ----
        #pragma unroll 2
        for (int kq = 0; kq < 8; kq++) {
            int k = kq*8;
            uint32_t a0 = xmu[(ctq*16 + gr    )*XMS + k + tc];
            uint32_t a1 = xmu[(ctq*16 + gr + 8)*XMS + k + tc];
            uint32_t a2 = xmu[(ctq*16 + gr    )*XMS + k + tc + 4];
            uint32_t a3 = xmu[(ctq*16 + gr + 8)*XMS + k + tc + 4];
            #pragma unroll
            for (int nt = 0; nt < 4; nt++) {
                int o0 = oh*32 + nt*8;
                uint32_t b0 = wu[(k + tc    )*WST + o0 + gr];
                uint32_t b1 = wu[(k + tc + 4)*WST + o0 + gr];
                mma_tf32(dY[nt], a0, a1, a2, a3, b0, b1);
            }
        }
    }

    // ---- epilogue ----
    {
        const int row0 = ctq*16 + gr;
        const int row1 = row0 + 8;
        const int colg0 = cbase + row0;
        const int colg1 = cbase + row1;
        const bool ok0 = (colg0 < NCOL);
        const bool ok1 = (colg1 < NCOL);
        float* on = out + (size_t)n*(CC*NCOL);
        #pragma unroll
        for (int nt = 0; nt < 4; nt++) {
            int oe = oh*32 + nt*8 + 2*tc;
            int oo = oe + 1;
            float offe = s_off[oe], offo = s_off[oo];
            if (ok0) {
                float v0 = dY[nt][0] + offe + xn[(size_t)oe*NCOL + colg0];
                float v1 = dY[nt][1] + offo + xn[(size_t)oo*NCOL + colg0];
                on[(size_t)oe*NCOL + colg0] = fmaxf(v0, 0.f);
                on[(size_t)oo*NCOL + colg0] = fmaxf(v1, 0.f);
            }
            if (ok1) {
                float v2 = dY[nt][2] + offe + xn[(size_t)oe*NCOL + colg1];
                float v3 = dY[nt][3] + offo + xn[(size_t)oo*NCOL + colg1];
                on[(size_t)oe*NCOL + colg1] = fmaxf(v2, 0.f);
                on[(size_t)oo*NCOL + colg1] = fmaxf(v3, 0.f);
            }
        }
    }
}

// ---------------------------------------------------------------------------
extern "C" void kernel_launch(void* const* d_in, const int* in_sizes, int n_in,
                              void* d_out, int out_size)
{
    const float* x     = (const float*)d_in[0];
    const float* A     = (const float*)d_in[1];
    const float* alpha = (const float*)d_in[2];
    const float* caw   = (const float*)d_in[3];
    const float* cab   = (const float*)d_in[4];
    const float* cbw   = (const float*)d_in[5];
    const float* cbb   = (const float*)d_in[6];
    const float* bag   = (const float*)d_in[7];
    const float* babt  = (const float*)d_in[8];
    const float* bam   = (const float*)d_in[9];
    const float* bav   = (const float*)d_in[10];
    const float* bbg   = (const float*)d_in[11];
    const float* bbbt  = (const float*)d_in[12];
    const float* bbm   = (const float*)d_in[13];
    const float* bbv   = (const float*)d_in[14];
    const float* cdw   = (const float*)d_in[15];
    const float* cdb   = (const float*)d_in[16];
    const float* bng   = (const float*)d_in[17];
    const float* bnb   = (const float*)d_in[18];
    const float* bnm   = (const float*)d_in[19];
    const float* bnv   = (const float*)d_in[20];
    float* out = (float*)d_out;

    const int smemB = (CT*XMS + CC*WST + 96*32 + 64) * sizeof(float);
    cudaFuncSetAttribute(kB, cudaFuncAttributeMaxDynamicSharedMemorySize, smemB);

    // launch order keeps kM as the 4th launch (ncu capture slot)
    kW<<<(SS*OCn*CC + 255)/256, 256>>>(cdw, cdb, bng, bnb, bnm, bnv);
    kConv<<<dim3(8, SS, NN), 256>>>(x, caw, cab, cbw, cbb,
                                    bag, babt, bam, bav,
                                    bbg, bbbt, bbm, bbv, 0);
    kConv<<<dim3(NTCB - 8, SS, NN), 256>>>(x, caw, cab, cbw, cbb,
                                           bag, babt, bam, bav,
                                           bbg, bbbt, bbm, bbv, 8);
    kM<<<dim3(NCH, SS, NN), 256>>>();
    kA2<<<(NN*96*32 + 255)/256, 256>>>(A, alpha);
    kB<<<dim3(NTBL, NN), 256, smemB>>>(x, out);
}

// round 14
// speedup vs baseline: 2.1850x; 1.0805x over previous
#include <cuda_runtime.h>
#include <cuda_bf16.h>
#include <cstdint>

#define EPSF 1e-5f

// Problem dims
#define NN  64
#define CC  64
#define TD  300
#define VV  25
#define SS  3
#define ICn 16
#define OCn 64
#define NCOL (TD*VV)          // 7500

// kConvM tiling
#define TCB   20
#define MCH   (TD/TCB)        // 15 chunks (also M split-k partials)
#define COLSB (TCB*VV)        // 500

// kB tiling
#define CT    64                      // cols per block
#define NTBL  ((NCOL + CT - 1)/CT)    // 118
#define XMS   68                      // xm row stride
#define WST   68                      // W row stride ([o][k], LDSM conflict-free)

typedef unsigned long long u64;

__device__ float g_Mpart[MCH*NN*SS*VV*VV];
__device__ float g_Afrag[(size_t)NN*96*32];  // A_adp in mma frag layout, tf32
__device__ float g_wdT  [SS*OCn*CC];         // [s][o][c], BN-scaled, tf32 bits
__device__ float g_off  [OCn];

__device__ __forceinline__ float tanh_fast(float x) {
    float y;
    asm("tanh.approx.f32 %0, %1;" : "=f"(y) : "f"(x));
    return y;
}
__device__ __forceinline__ uint32_t f2tf32(float x) {
    uint32_t u;
    asm("cvt.rna.tf32.f32 %0, %1;" : "=r"(u) : "f"(x));
    return u;
}
__device__ __forceinline__ uint32_t prmt(uint32_t a, uint32_t b, uint32_t sel) {
    uint32_t d;
    asm("prmt.b32 %0, %1, %2, %3;" : "=r"(d) : "r"(a), "r"(b), "r"(sel));
    return d;
}
__device__ __forceinline__ uint32_t bfpack(float lo, float hi) {
    __nv_bfloat162 h = __floats2bfloat162_rn(lo, hi);
    return *reinterpret_cast<uint32_t*>(&h);
}
__device__ __forceinline__ void mma_tf32(float d[4],
    uint32_t a0, uint32_t a1, uint32_t a2, uint32_t a3,
    uint32_t b0, uint32_t b1)
{
    asm volatile(
        "mma.sync.aligned.m16n8k8.row.col.f32.tf32.tf32.f32 "
        "{%0,%1,%2,%3}, {%4,%5,%6,%7}, {%8,%9}, {%0,%1,%2,%3};\n"
        : "+f"(d[0]), "+f"(d[1]), "+f"(d[2]), "+f"(d[3])
        : "r"(a0), "r"(a1), "r"(a2), "r"(a3), "r"(b0), "r"(b1));
}
__device__ __forceinline__ void mma_bf16(float d[4],
    uint32_t a0, uint32_t a1, uint32_t a2, uint32_t a3,
    uint32_t b0, uint32_t b1)
{
    asm volatile(
        "mma.sync.aligned.m16n8k16.row.col.f32.bf16.bf16.f32 "
        "{%0,%1,%2,%3}, {%4,%5,%6,%7}, {%8,%9}, {%0,%1,%2,%3};\n"
        : "+f"(d[0]), "+f"(d[1]), "+f"(d[2]), "+f"(d[3])
        : "r"(a0), "r"(a1), "r"(a2), "r"(a3), "r"(b0), "r"(b1));
}
__device__ __forceinline__ void ldsm4(uint32_t r[4], uint32_t addr)
{
    asm volatile(
        "ldmatrix.sync.aligned.m8n8.x4.shared.b16 {%0,%1,%2,%3}, [%4];"
        : "=r"(r[0]), "=r"(r[1]), "=r"(r[2]), "=r"(r[3]) : "r"(addr));
}

// ---------------------------------------------------------------------------
// kConvM: per (chunk of 20 t, s, n):
//  Phase 1 (tf32 mma): D[io][col] = sum_c Wab[io][c]*x[c][col]; tanh; pack
//    bf16 mma fragments into smem (s_fr) via shfl/prmt.
//  Phase 2 (bf16 mma): partial M[v,w] over the 20 k16-steps; smem reduction;
//    store g_Mpart[chunk].
// ---------------------------------------------------------------------------
__global__ __launch_bounds__(256, 2) void kConvM(
    const float* __restrict__ x,
    const float* __restrict__ wa, const float* __restrict__ ba,
    const float* __restrict__ wb, const float* __restrict__ bb,
    const float* __restrict__ gag, const float* __restrict__ gab,
    const float* __restrict__ gam, const float* __restrict__ gav,
    const float* __restrict__ gbg, const float* __restrict__ gbb,
    const float* __restrict__ gbm, const float* __restrict__ gbv)
{
    // s_fr: 2*20*256 u32 = 40 KB. Reused as: (1) weight tf32 staging,
    // (2) a/b fragment store, (3) reduction buffer.
    __shared__ __align__(16) uint32_t s_fr[2*TCB*256];
    __shared__ float s_sh[32];

    uint32_t* s_aF = s_fr;
    uint32_t* s_bF = s_fr + TCB*256;
    float*    s_wf = reinterpret_cast<float*>(s_fr);   // 32*68 < 2*TCB*256

    const int tid  = threadIdx.x;
    const int wid  = tid >> 5;
    const int lane = tid & 31;
    const int gr   = lane >> 2;
    const int tc   = lane & 3;
    const int chunk = blockIdx.x;
    const int s     = blockIdx.y;
    const int n     = blockIdx.z;

    // ---- fold BN into weights (tf32) + shifts ----
    for (int idx = tid; idx < 32*CC; idx += 256) {
        int io = idx >> 6, c = idx & 63;
        int i  = io & 15;
        bool isB = io >= 16;
        float g  = isB ? gbg[s*ICn+i] : gag[s*ICn+i];
        float vv = isB ? gbv[s*ICn+i] : gav[s*ICn+i];
        float wv = isB ? wb[s*ICn*CC + i*CC + c] : wa[s*ICn*CC + i*CC + c];
        float sc = g * rsqrtf(vv + EPSF);
        s_wf[io*68 + c] = __uint_as_float(f2tf32(wv * sc));
    }
    if (tid < 32) {
        int i = tid & 15;
        bool isB = tid >= 16;
        float g  = isB ? gbg[s*ICn+i] : gag[s*ICn+i];
        float vv = isB ? gbv[s*ICn+i] : gav[s*ICn+i];
        float bs = isB ? bb[s*ICn+i]  : ba[s*ICn+i];
        float mn = isB ? gbm[s*ICn+i] : gam[s*ICn+i];
        float bt = isB ? gbb[s*ICn+i] : gab[s*ICn+i];
        float sc = g * rsqrtf(vv + EPSF);
        s_sh[tid] = (bs - mn) * sc + bt;
    }
    __syncthreads();

    // hoist weight A-fragments to registers
    const uint32_t* wfu = reinterpret_cast<const uint32_t*>(s_wf);
    uint32_t af[2][8][4];
    #pragma unroll
    for (int mi = 0; mi < 2; mi++)
        #pragma unroll
        for (int kt = 0; kt < 8; kt++) {
            int r0 = (mi*16 + gr)*68 + kt*8 + tc;
            af[mi][kt][0] = wfu[r0];
            af[mi][kt][1] = wfu[r0 + 8*68];
            af[mi][kt][2] = wfu[r0 + 4];
            af[mi][kt][3] = wfu[r0 + 8*68 + 4];
        }
    const float sha0 = s_sh[gr],      sha8 = s_sh[gr + 8];
    const float shb0 = s_sh[16 + gr], shb8 = s_sh[24 + gr];
    __syncthreads();   // done reading s_wf

    // zero fragment buffer (pad slots must be 0 for the M mma)
    for (int idx = tid; idx < 2*TCB*256; idx += 256) s_fr[idx] = 0u;
    __syncthreads();

    // ---- Phase 1: conv + tanh -> fragments in smem ----
    const float* xn = x + (size_t)n*(CC*NCOL);
    const int lwbase = wid*64;
    const int tck = gr >> 1;
    const bool evenGr = ((gr & 1) == 0);

    #pragma unroll 2
    for (int nt = 0; nt < 8; nt++) {
        const int n0 = nt*8;
        const int lcol = lwbase + n0 + gr;
        const bool ld  = (lcol < COLSB);
        const int colg = chunk*COLSB + lcol;

        uint32_t bf[8][2];
        const float* xp = xn + colg;
        #pragma unroll
        for (int kt = 0; kt < 8; kt++) {
            float v0 = ld ? xp[(size_t)(kt*8 + tc)*NCOL]     : 0.f;
            float v1 = ld ? xp[(size_t)(kt*8 + tc + 4)*NCOL] : 0.f;
            bf[kt][0] = f2tf32(v0);
            bf[kt][1] = f2tf32(v1);
        }

        float da[4] = {0.f, 0.f, 0.f, 0.f};
        float dbv[4] = {0.f, 0.f, 0.f, 0.f};
        #pragma unroll
        for (int kt = 0; kt < 8; kt++) {
            mma_tf32(da,  af[0][kt][0], af[0][kt][1], af[0][kt][2], af[0][kt][3],
                     bf[kt][0], bf[kt][1]);
            mma_tf32(dbv, af[1][kt][0], af[1][kt][1], af[1][kt][2], af[1][kt][3],
                     bf[kt][0], bf[kt][1]);
        }

        uint32_t ha  = bfpack(tanh_fast(da[0]  + sha0), tanh_fast(da[1]  + sha0));
        uint32_t ha8 = bfpack(tanh_fast(da[2]  + sha8), tanh_fast(da[3]  + sha8));
        uint32_t hb  = bfpack(tanh_fast(dbv[0] + shb0), tanh_fast(dbv[1] + shb0));
        uint32_t hb8 = bfpack(tanh_fast(dbv[2] + shb8), tanh_fast(dbv[3] + shb8));

        uint32_t pa  = __shfl_xor_sync(0xffffffffu, ha,  4);
        uint32_t pa8 = __shfl_xor_sync(0xffffffffu, ha8, 4);
        uint32_t pb  = __shfl_xor_sync(0xffffffffu, hb,  4);
        uint32_t pb8 = __shfl_xor_sync(0xffffffffu, hb8, 4);

        const int lc0 = lwbase + n0 + 2*tc;

        if (evenGr) {
            uint32_t wlo0 = prmt(ha,  pa,  0x5410);
            uint32_t whi0 = prmt(ha8, pa8, 0x5410);
            uint32_t wlo1 = prmt(ha,  pa,  0x7632);
            uint32_t whi1 = prmt(ha8, pa8, 0x7632);
            #pragma unroll
            for (int cc2 = 0; cc2 < 2; cc2++) {
                int lc = lc0 + cc2;
                if (lc < COLSB) {
                    int tl = lc / 25, v = lc - 25*tl;
                    int mt = v >> 4, vt = v & 15;
                    int rsel = vt >> 3, grt = vt & 7;
                    uint32_t wlo = cc2 ? wlo1 : wlo0;
                    uint32_t whi = cc2 ? whi1 : whi0;
                    s_aF[tl*256 + (mt*4 + rsel    )*32 + grt*4 + tck] = wlo;
                    s_aF[tl*256 + (mt*4 + 2 + rsel)*32 + grt*4 + tck] = whi;
                }
            }
        } else {
            uint32_t wlo0 = prmt(pb,  hb,  0x5410);
            uint32_t whi0 = prmt(pb8, hb8, 0x5410);
            uint32_t wlo1 = prmt(pb,  hb,  0x7632);
            uint32_t whi1 = prmt(pb8, hb8, 0x7632);
            #pragma unroll
            for (int cc2 = 0; cc2 < 2; cc2++) {
                int lc = lc0 + cc2;
                if (lc < COLSB) {
                    int tl = lc / 25, v = lc - 25*tl;
                    int wt = v >> 3, grw = v & 7;
                    uint32_t wlo = cc2 ? wlo1 : wlo0;
                    uint32_t whi = cc2 ? whi1 : whi0;
                    s_bF[tl*256 + (wt*2    )*32 + grw*4 + tck] = wlo;
                    s_bF[tl*256 + (wt*2 + 1)*32 + grw*4 + tck] = whi;
                }
            }
        }
    }
    __syncthreads();

    // ---- Phase 2: bf16 mma over 20 k16-steps (8-warp split-k) ----
    float acc[2][4][4];
    #pragma unroll
    for (int mt = 0; mt < 2; mt++)
        #pragma unroll
        for (int wt = 0; wt < 4; wt++)
            #pragma unroll
            for (int r = 0; r < 4; r++) acc[mt][wt][r] = 0.f;

    for (int ls = wid; ls < TCB; ls += 8) {
        const uint32_t* pa = s_aF + ls*256 + lane;
        const uint32_t* pb = s_bF + ls*256 + lane;
        uint32_t aw[2][4], bw[4][2];
        #pragma unroll
        for (int mt = 0; mt < 2; mt++)
            #pragma unroll
            for (int r = 0; r < 4; r++)
                aw[mt][r] = pa[(mt*4 + r)*32];
        #pragma unroll
        for (int wt = 0; wt < 4; wt++)
            #pragma unroll
            for (int r = 0; r < 2; r++)
                bw[wt][r] = pb[(wt*2 + r)*32];
        #pragma unroll
        for (int mt = 0; mt < 2; mt++)
            #pragma unroll
            for (int wt = 0; wt < 4; wt++)
                mma_bf16(acc[mt][wt], aw[mt][0], aw[mt][1], aw[mt][2], aw[mt][3],
                         bw[wt][0], bw[wt][1]);
    }
    __syncthreads();   // everyone done reading s_fr

    // ---- reduction across 8 warps (reuse s_fr as float buffer) ----
    float* s_red = reinterpret_cast<float*>(s_fr);
    float* my = s_red + wid*1024;
    #pragma unroll
    for (int mt = 0; mt < 2; mt++)
        #pragma unroll
        for (int wt = 0; wt < 4; wt++)
            #pragma unroll
            for (int r = 0; r < 4; r++)
                my[((mt*4 + wt)*4 + r)*32 + lane] = acc[mt][wt][r];
    __syncthreads();

    #pragma unroll
    for (int rep = 0; rep < 4; rep++) {
        int pos = tid + rep*256;
        float v = 0.f;
        #pragma unroll
        for (int w8 = 0; w8 < 8; w8++)
            v += s_red[w8*1024 + pos];
        int lp  = pos & 31;
        int reg = (pos >> 5) & 3;
        int wt  = (pos >> 7) & 3;
        int mt  = pos >> 9;
        int grp = lp >> 2, tcp = lp & 3;
        int vv = mt*16 + grp + (reg >> 1)*8;
        int ww = wt*8 + 2*tcp + (reg & 1);
        if (vv < VV && ww < VV)
            g_Mpart[((size_t)chunk*NN*SS + (size_t)n*SS + s)*(VV*VV)
                    + vv*VV + ww] = v;
    }
}

// ---------------------------------------------------------------------------
// kA2: reduce partials, A_adp = A + tanh(M/(IC*T))*alpha, emitted in kB's
// mma fragment layout.
// ---------------------------------------------------------------------------
__global__ void kA2(const float* __restrict__ A, const float* __restrict__ alpha)
{
    int idx = blockIdx.x * 256 + threadIdx.x;
    if (idx >= NN*96*32) return;
    int lane = idx & 31;
    int r    = (idx >> 5) % 96;
    int n    = idx / (96*32);
    int reg = r & 1;
    int wt  = (r >> 1) & 3;
    int kt  = (r >> 3) & 3;
    int s   = r >> 5;
    int v = kt*8 + (lane & 3) + reg*4;
    int w = wt*8 + (lane >> 2);
    float val = 0.f;
    if (v < VV && w < VV) {
        int mi = (n*SS + s)*(VV*VV) + v*VV + w;
        float m = 0.f;
        #pragma unroll
        for (int ch = 0; ch < MCH; ch++)
            m += g_Mpart[ch*(NN*SS*VV*VV) + mi];
        val = A[s*(VV*VV) + v*VV + w]
            + tanhf(m * (1.f/(float)(ICn*TD))) * alpha[0];
    }
    g_Afrag[idx] = __uint_as_float(f2tf32(val));
}

// ---------------------------------------------------------------------------
// kW: W -> [s][o][c] (native layout), BN scale folded, tf32-rounded. g_off.
// ---------------------------------------------------------------------------
__global__ void kW(const float* __restrict__ wd, const float* __restrict__ db,
                   const float* __restrict__ bng, const float* __restrict__ bnb,
                   const float* __restrict__ bnm, const float* __restrict__ bnv)
{
    int idx = blockIdx.x * 256 + threadIdx.x;
    if (idx < SS*OCn*CC) {
        int o = (idx >> 6) & 63;
        float sc = bng[o] * rsqrtf(bnv[o] + EPSF);
        g_wdT[idx] = __uint_as_float(f2tf32(wd[idx] * sc));
    }
    if (blockIdx.x == 0 && threadIdx.x < OCn) {
        int o = threadIdx.x;
        float sc = bng[o] * rsqrtf(bnv[o] + EPSF);
        float ds = db[o] + db[OCn + o] + db[2*OCn + o];
        g_off[o] = (ds - bnm[o]) * sc + bnb[o];
    }
}

// ---------------------------------------------------------------------------
// kB: block = (64-col tile, n), 4 blocks/SM. For each s:
//   GEMM1 (mma tf32): xm[col][c], x frags reg-resident
//   GEMM2 (mma tf32): D[col][o] += xm @ W_s; fragments via ldmatrix.x4
// Epilogue: D + off + residual, ReLU.
// ---------------------------------------------------------------------------
__global__ __launch_bounds__(256, 4) void kB(
    const float* __restrict__ x,
    float* __restrict__ out)
{
    extern __shared__ float sm[];
    float* s_xm  = sm;                  // [64][68]  tf32 bits
    float* s_w   = s_xm + CT*XMS;       // [64][68]  tf32 bits, [o][k] per s
    float* s_Af  = s_w  + OCn*WST;      // [96][32]  A_adp frags, tf32
    float* s_off = s_Af + 96*32;        // [64]

    const int tid  = threadIdx.x;
    const int wid  = tid >> 5;
    const int lane = tid & 31;
    const int gr   = lane >> 2;
    const int tc   = lane & 3;
    const int blk  = blockIdx.x;
    const int n    = blockIdx.y;
    const int cbase = blk * CT;
    const int t0    = cbase / VV;
    const int coff  = cbase - t0*VV;

    const float* xn = x + (size_t)n*(CC*NCOL);

    // ---- prologue staging ----
    {
        const float4* ag = reinterpret_cast<const float4*>(
            g_Afrag + (size_t)n*(96*32));
        float4* as = reinterpret_cast<float4*>(s_Af);
        for (int idx = tid; idx < 96*32/4; idx += 256)
            as[idx] = ag[idx];
    }
    if (tid < OCn) s_off[tid] = g_off[tid];

    // warp roles
    const int tl = wid & 3;
    const int oh = wid >> 2;
    const int ctq = wid & 3;

    // x A-fragments in registers (s-invariant)
    uint32_t ax[2][4][4];
    {
        const int colB = (t0 + tl)*VV;
        #pragma unroll
        for (int mi = 0; mi < 2; mi++) {
            const int r0 = (oh + 2*mi)*16 + gr;
            const float* b0p = xn + (size_t)r0*NCOL;
            const float* b1p = b0p + (size_t)8*NCOL;
            #pragma unroll
            for (int kt = 0; kt < 4; kt++) {
                int c0i = colB + kt*8 + tc;
                int c1i = c0i + 4;
                bool k0 = (c0i < NCOL);
                bool k1 = (c1i < NCOL);
                ax[mi][kt][0] = f2tf32(k0 ? b0p[c0i] : 0.f);
                ax[mi][kt][1] = f2tf32(k0 ? b1p[c0i] : 0.f);
                ax[mi][kt][2] = f2tf32(k1 ? b0p[c1i] : 0.f);
                ax[mi][kt][3] = f2tf32(k1 ? b1p[c1i] : 0.f);
            }
        }
    }
    __syncthreads();   // s_Af ready

    const uint32_t* afu = reinterpret_cast<const uint32_t*>(s_Af);
    uint32_t* xmw = reinterpret_cast<uint32_t*>(s_xm);

    // ldmatrix base addresses (bytes)
    const uint32_t xm_sa = (uint32_t)__cvta_generic_to_shared(s_xm);
    const uint32_t w_sa  = (uint32_t)__cvta_generic_to_shared(s_w);
    const uint32_t addrA = xm_sa
        + (((ctq*16 + (lane & 15))*XMS + ((lane >> 4) << 2)) << 2);
    const uint32_t addrB = w_sa
        + (((oh*32 + ((lane >> 4) << 3) + (lane & 7))*WST
            + (((lane >> 3) & 1) << 2)) << 2);

    float dY[4][4];
    #pragma unroll
    for (int nt = 0; nt < 4; nt++)
        #pragma unroll
        for (int j = 0; j < 4; j++) dY[nt][j] = 0.f;

    for (int s = 0; s < SS; s++) {
        if (s) __syncthreads();
        // stage W_s: [o][k], float4 coalesced
        {
            const float4* wg = reinterpret_cast<const float4*>(
                g_wdT + s*(OCn*CC));
            for (int idx = tid; idx < OCn*CC/4; idx += 256) {
                int o = idx >> 4, c4 = (idx & 15) << 2;
                *reinterpret_cast<float4*>(&s_w[o*WST + c4]) = wg[idx];
            }
        }

        // ---- GEMM1 via mma: xm[col][c] from reg-resident x frags ----
        #pragma unroll
        for (int mi = 0; mi < 2; mi++) {
            const int c0 = (oh + 2*mi)*16;
            #pragma unroll
            for (int wt = 0; wt < 4; wt++) {
                float d[4] = {0.f, 0.f, 0.f, 0.f};
                #pragma unroll
                for (int kt = 0; kt < 4; kt++) {
                    int fb = (((s*4 + kt)*4 + wt)*2)*32 + lane;
                    mma_tf32(d, ax[mi][kt][0], ax[mi][kt][1],
                                ax[mi][kt][2], ax[mi][kt][3],
                                afu[fb], afu[fb + 32]);
                }
                int w0  = wt*8 + 2*tc;
                int lc0 = tl*VV + w0 - coff;
                if (w0 < VV && lc0 >= 0 && lc0 < CT) {
                    xmw[lc0*XMS + c0 + gr]     = f2tf32(d[0]);
                    xmw[lc0*XMS + c0 + gr + 8] = f2tf32(d[2]);
                }
                int w1  = w0 + 1;
                int lc1 = lc0 + 1;
                if (w1 < VV && lc1 >= 0 && lc1 < CT) {
                    xmw[lc1*XMS + c0 + gr]     = f2tf32(d[1]);
                    xmw[lc1*XMS + c0 + gr + 8] = f2tf32(d[3]);
                }
            }
        }
        __syncthreads();

        // ---- GEMM2 via mma: K = 64 (this s); frags via ldmatrix ----
        #pragma unroll 2
        for (int kq = 0; kq < 8; kq++) {
            const uint32_t koff = (uint32_t)(kq*8) << 2;
            uint32_t a[4], b01[4], b23[4];
            ldsm4(a,   addrA + koff);
            ldsm4(b01, addrB + koff);
            ldsm4(b23, addrB + (16*WST << 2) + koff);
            mma_tf32(dY[0], a[0], a[1], a[2], a[3], b01[0], b01[1]);
            mma_tf32(dY[1], a[0], a[1], a[2], a[3], b01[2], b01[3]);
            mma_tf32(dY[2], a[0], a[1], a[2], a[3], b23[0], b23[1]);
            mma_tf32(dY[3], a[0], a[1], a[2], a[3], b23[2], b23[3]);
        }
    }

    // ---- epilogue ----
    {
        const int row0 = ctq*16 + gr;
        const int row1 = row0 + 8;
        const int colg0 = cbase + row0;
        const int colg1 = cbase + row1;
        const bool ok0 = (colg0 < NCOL);
        const bool ok1 = (colg1 < NCOL);
        float* on = out + (size_t)n*(CC*NCOL);
        #pragma unroll
        for (int nt = 0; nt < 4; nt++) {
            int oe = oh*32 + nt*8 + 2*tc;
            int oo = oe + 1;
            float offe = s_off[oe], offo = s_off[oo];
            if (ok0) {
                float v0 = dY[nt][0] + offe + xn[(size_t)oe*NCOL + colg0];
                float v1 = dY[nt][1] + offo + xn[(size_t)oo*NCOL + colg0];
                on[(size_t)oe*NCOL + colg0] = fmaxf(v0, 0.f);
                on[(size_t)oo*NCOL + colg0] = fmaxf(v1, 0.f);
            }
            if (ok1) {
                float v2 = dY[nt][2] + offe + xn[(size_t)oe*NCOL + colg1];
                float v3 = dY[nt][3] + offo + xn[(size_t)oo*NCOL + colg1];
                on[(size_t)oe*NCOL + colg1] = fmaxf(v2, 0.f);
                on[(size_t)oo*NCOL + colg1] = fmaxf(v3, 0.f);
            }
        }
    }
}

// ---------------------------------------------------------------------------
extern "C" void kernel_launch(void* const* d_in, const int* in_sizes, int n_in,
                              void* d_out, int out_size)
{
    const float* x     = (const float*)d_in[0];
    const float* A     = (const float*)d_in[1];
    const float* alpha = (const float*)d_in[2];
    const float* caw   = (const float*)d_in[3];
    const float* cab   = (const float*)d_in[4];
    const float* cbw   = (const float*)d_in[5];
    const float* cbb   = (const float*)d_in[6];
    const float* bag   = (const float*)d_in[7];
    const float* babt  = (const float*)d_in[8];
    const float* bam   = (const float*)d_in[9];
    const float* bav   = (const float*)d_in[10];
    const float* bbg   = (const float*)d_in[11];
    const float* bbbt  = (const float*)d_in[12];
    const float* bbm   = (const float*)d_in[13];
    const float* bbv   = (const float*)d_in[14];
    const float* cdw   = (const float*)d_in[15];
    const float* cdb   = (const float*)d_in[16];
    const float* bng   = (const float*)d_in[17];
    const float* bnb   = (const float*)d_in[18];
    const float* bnm   = (const float*)d_in[19];
    const float* bnv   = (const float*)d_in[20];
    float* out = (float*)d_out;

    const int smemB = (CT*XMS + OCn*WST + 96*32 + 64) * sizeof(float);
    cudaFuncSetAttribute(kB, cudaFuncAttributeMaxDynamicSharedMemorySize, smemB);

    // 4 launches: kB is the 4th (ncu capture slot)
    kW<<<(SS*OCn*CC + 255)/256, 256>>>(cdw, cdb, bng, bnb, bnm, bnv);
    kConvM<<<dim3(MCH, SS, NN), 256>>>(x, caw, cab, cbw, cbb,
                                       bag, babt, bam, bav,
                                       bbg, bbbt, bbm, bbv);
    kA2<<<(NN*96*32 + 255)/256, 256>>>(A, alpha);
    kB<<<dim3(NTBL, NN), 256, smemB>>>(x, out);
}